// round 6
// baseline (speedup 1.0000x reference)
#include <cuda_runtime.h>
#include <cstdint>
#include <math.h>

// ---------------------------------------------------------------------------
// Problem constants
// ---------------------------------------------------------------------------
static constexpr int kB = 8;
static constexpr int kS = 2048;
static constexpr int kD = 256;
static constexpr int kM = kB * kS;
static constexpr int WCH = 512;      // colsum partial chunks (4 rows per warp)
static constexpr int N_KCHUNK = 32;  // output split over keys

// Scratch (static device memory)
__device__ float g_NR[kM * kD];              // tf32-rounded nodes
__device__ float g_WqR[kD * kD];
__device__ float g_WkR[kD * kD];
__device__ float g_WvR[kD * kD];
__device__ float g_Q[kB * kS * kD];          // tf32-rounded q
__device__ float g_K[kB * kS * kD];          // tf32-rounded k
__device__ float g_V[kB * kS * kD];          // fp32 v
__device__ float g_P[(size_t)kB * kS * kS];  // masked scaled scores
__device__ float g_w[kB * kS];
__device__ float g_wpart[(size_t)WCH * kB * kS];   // 32 MB
__device__ float g_opart[N_KCHUNK * kB * kD];

#if defined(__CUDA_ARCH__) && defined(__CUDA_ARCH_FEAT_SM103_ALL)
#define HAS_TCGEN05 1
#else
#define HAS_TCGEN05 0
#endif

#define SMEM_SWIZZLE_128B(byte_offset) \
    ((byte_offset) ^ (((byte_offset) >> 3) & 0x70))

__device__ __forceinline__ uint32_t smem_to_u32_gen(const void* p) {
    uint32_t a;
    asm("{ .reg .u64 t; cvta.to.shared.u64 t, %1; cvt.u32.u64 %0, t; }"
        : "=r"(a) : "l"(p));
    return a;
}

__device__ __forceinline__ float to_tf32(float x) {
    float y;
    asm("cvt.rna.tf32.f32 %0, %1;" : "=f"(y) : "f"(x));
    return y;
}

#if HAS_TCGEN05
__device__ __forceinline__ uint32_t elect_one_pred() {
    uint32_t pred;
    asm volatile(
        "{\n\t.reg .pred p;\n\t"
        "elect.sync _|p, 0xFFFFFFFF;\n\t"
        "selp.b32 %0, 1, 0, p;\n\t}"
        : "=r"(pred));
    return pred;
}

#define TCGEN05_ALLOC(smem_result_addr, nCols) \
    asm volatile("tcgen05.alloc.cta_group::1.sync.aligned.shared::cta.b32 [%0], %1;" \
                 :: "r"((uint32_t)(smem_result_addr)), "r"((uint32_t)(nCols)) : "memory")
#define TCGEN05_DEALLOC(tmem_addr, nCols) \
    asm volatile("tcgen05.dealloc.cta_group::1.sync.aligned.b32 %0, %1;" \
                 :: "r"(tmem_addr), "r"((uint32_t)(nCols)))
#define TCGEN05_RELINQUISH() \
    asm volatile("tcgen05.relinquish_alloc_permit.cta_group::1.sync.aligned;")
#define TCGEN05_COMMIT(mbar_smem_addr) \
    asm volatile("tcgen05.commit.cta_group::1.mbarrier::arrive::one.shared::cluster.b64 [%0];" \
                 :: "r"((uint32_t)(mbar_smem_addr)) : "memory")
#define TCGEN05_FENCE_AFTER() \
    asm volatile("tcgen05.fence::after_thread_sync;" ::: "memory")
#define TCGEN05_WAIT_LD() \
    asm volatile("tcgen05.wait::ld.sync.aligned;" ::: "memory")
#define MBARRIER_INIT(mbar_smem_addr, count) \
    asm volatile("mbarrier.init.shared.b64 [%0], %1;" \
                 :: "r"((uint32_t)(mbar_smem_addr)), "r"((uint32_t)(count)) : "memory")
#define FENCE_PROXY_ASYNC_SHARED_CTA() \
    asm volatile("fence.proxy.async.shared::cta;" ::: "memory")

#define MBARRIER_WAIT_PARITY(mbar_smem_addr, phase_parity) do { \
    uint32_t _mbar = (uint32_t)(mbar_smem_addr); \
    uint32_t _parity = (uint32_t)(phase_parity); \
    uint32_t _done; \
    asm volatile( \
        "{\n\t.reg .pred p;\n\t" \
        "mbarrier.try_wait.parity.acquire.cta.shared::cta.b64 p, [%1], %2;\n\t" \
        "selp.b32 %0, 1, 0, p;\n\t}" \
        : "=r"(_done) : "r"(_mbar), "r"(_parity) : "memory"); \
    if (!_done) { \
        asm volatile( \
            "{\n\t.reg .pred P1;\n\t" \
            "WAIT_LOOP_%=:\n\t" \
            "mbarrier.try_wait.parity.acquire.cta.shared::cta.b64 P1, [%0], %1, 0x989680;\n\t" \
            "@P1 bra.uni WAIT_DONE_%=;\n\t" \
            "bra.uni WAIT_LOOP_%=;\n\t" \
            "WAIT_DONE_%=:\n\t}" \
            :: "r"(_mbar), "r"(_parity) : "memory"); \
    } \
} while(0)

#define TCGEN05_LD_32X32B_X32(r, tmem_addr) \
    asm volatile( \
        "tcgen05.ld.sync.aligned.32x32b.x32.b32 " \
        "{%0, %1, %2, %3, %4, %5, %6, %7, " \
        " %8, %9, %10, %11, %12, %13, %14, %15, " \
        " %16, %17, %18, %19, %20, %21, %22, %23, " \
        " %24, %25, %26, %27, %28, %29, %30, %31}, [%32];" \
        : "=r"((r)[0]),  "=r"((r)[1]),  "=r"((r)[2]),  "=r"((r)[3]), \
          "=r"((r)[4]),  "=r"((r)[5]),  "=r"((r)[6]),  "=r"((r)[7]), \
          "=r"((r)[8]),  "=r"((r)[9]),  "=r"((r)[10]), "=r"((r)[11]), \
          "=r"((r)[12]), "=r"((r)[13]), "=r"((r)[14]), "=r"((r)[15]), \
          "=r"((r)[16]), "=r"((r)[17]), "=r"((r)[18]), "=r"((r)[19]), \
          "=r"((r)[20]), "=r"((r)[21]), "=r"((r)[22]), "=r"((r)[23]), \
          "=r"((r)[24]), "=r"((r)[25]), "=r"((r)[26]), "=r"((r)[27]), \
          "=r"((r)[28]), "=r"((r)[29]), "=r"((r)[30]), "=r"((r)[31]) \
        : "r"(tmem_addr))

#define TCGEN05_MMA_TF32_SS(d_tmem, a_desc, b_desc, idesc, enable_d) do { \
    uint32_t _en = (enable_d) ? 1u : 0u; \
    uint32_t _zero = 0u; \
    asm volatile( \
        "{\n\t.reg .pred p;\n\t" \
        "setp.ne.u32 p, %5, 0;\n\t" \
        "tcgen05.mma.cta_group::1.kind::tf32 [%0], %1, %2, %3, {%4, %4, %4, %4}, p;\n\t" \
        "}" \
        :: "r"(d_tmem), "l"(a_desc), "l"(b_desc), "r"(idesc), "r"(_zero), "r"(_en) \
        : "memory"); \
} while(0)

static constexpr uint64_t SMEM_DESC_BASE_SW128 =
    (uint64_t(2)  << 61) | (uint64_t(1) << 46) | (uint64_t(64) << 32) | (uint64_t(1) << 16);
#define MAKE_SMEM_DESC(base_addr) \
    (SMEM_DESC_BASE_SW128 | ((uint64_t)((base_addr) >> 4) & 0x3FFF))

__device__ __forceinline__ void cp_async16(uint32_t dst, const void* src) {
    asm volatile("cp.async.cg.shared.global [%0], [%1], 16;" :: "r"(dst), "l"(src));
}
#define CPASYNC_MBAR_ARRIVE_NOINC(mbar) \
    asm volatile("cp.async.mbarrier.arrive.noinc.shared::cta.b64 [%0];" \
                 :: "r"((uint32_t)(mbar)) : "memory")

// IDESC for tf32, F32 accum, M=128, N=256
static constexpr uint32_t IDESC_128x256 =
    (1u << 4) | (2u << 7) | (2u << 10) | ((256 / 8) << 17) | ((128 / 16) << 24);
#endif  // HAS_TCGEN05

// ---------------------------------------------------------------------------
// Pre-round to tf32 (rna)
// ---------------------------------------------------------------------------
__global__ __launch_bounds__(256)
void rnd_kernel(const float* __restrict__ src, float* __restrict__ dst)
{
    const int i = blockIdx.x * 256 + threadIdx.x;
    dst[i] = to_tf32(src[i]);
}

// ---------------------------------------------------------------------------
// Unified pipelined single-tf32 tcgen05 GEMM, BM=256, BN=256, K=256.
//   C[m,n] = sum_k A[m,k] * B[n,k]  (A, B already tf32-valued fp32)
// mode 0: C = tf32(acc + bias)   (Q, K projections)
// mode 1: C = acc + bias         (V projection)
// mode 2: C = acc*scale, masked n -> -inf   (scores)
// smem: [0,8) full0 [8,16) full1 [16,24) emp0 [24,32) emp1 [32,40) done
//       [40,44) tmem, [64,1088) mask[256], [1088,2112) bias[256]
//       [4096..) 2 stages x {A0 16K | A1 16K | B 32K}
// ---------------------------------------------------------------------------
static constexpr int PG_STAGE = 65536;
static constexpr int PG_SMEM = 4096 + 2 * PG_STAGE;   // 135168

__global__ __launch_bounds__(256)
void pipe_gemm(const float* __restrict__ A, const float* __restrict__ Bm,
               const float* __restrict__ bias, const int* __restrict__ mask,
               float* __restrict__ C, int N, int mode,
               long long strideA, long long strideB, long long strideC,
               int maskStride, float scale)
{
    extern __shared__ __align__(1024) char smem[];
    const int tid = threadIdx.x;
    const int bz = blockIdx.z;
    constexpr int K = 256;
    A  += (size_t)bz * strideA;
    Bm += (size_t)bz * strideB;
    C  += (size_t)bz * strideC;
    if (mask) mask += (size_t)bz * maskStride;

    const int bm = blockIdx.y * 256;
    const int bn = blockIdx.x * 256;
    const float NEG_INF = __int_as_float(0xff800000u);

#if HAS_TCGEN05
    const uint32_t sb = smem_to_u32_gen(smem);
    const uint32_t m_full0 = sb + 0,  m_full1 = sb + 8;
    const uint32_t m_emp0  = sb + 16, m_emp1  = sb + 24;
    const uint32_t m_done  = sb + 32;
    int*   s_mask = (int*)(smem + 64);
    float* s_bias = (float*)(smem + 1088);
    const int wid = tid >> 5;

    if (wid == 0) { TCGEN05_ALLOC(sb + 40, 512); TCGEN05_RELINQUISH(); }
    if (tid == 0) {
        MBARRIER_INIT(m_full0, 256);
        MBARRIER_INIT(m_full1, 256);
        MBARRIER_INIT(m_emp0, 1);
        MBARRIER_INIT(m_emp1, 1);
        MBARRIER_INIT(m_done, 1);
    }
    if (mode == 2) s_mask[tid] = mask[bn + tid];
    else           s_bias[tid] = bias[bn + tid];
    __syncthreads();
    const uint32_t tmem = *(volatile uint32_t*)(smem + 40);

    uint64_t dA0[2], dA1[2], dB[2];
#pragma unroll
    for (int s = 0; s < 2; s++) {
        uint32_t base = sb + 4096 + s * PG_STAGE;
        dA0[s] = MAKE_SMEM_DESC(base);
        dA1[s] = MAKE_SMEM_DESC(base + 16384);
        dB[s]  = MAKE_SMEM_DESC(base + 32768);
    }

    for (int c = 0; c < K / 32; c++) {
        const int s = c & 1;
        const int i = c >> 1;
        const int k0 = c * 32;
        const uint32_t m_full = s ? m_full1 : m_full0;
        const uint32_t m_emp  = s ? m_emp1  : m_emp0;
        const uint32_t st = sb + 4096 + s * PG_STAGE;

        MBARRIER_WAIT_PARITY(m_emp, 1 ^ (i & 1));
        // A: 256 rows x 32 cols = 2048 float4; rows 0-127 -> A0, 128-255 -> A1
#pragma unroll
        for (int t = 0; t < 8; t++) {
            int idx = tid + t * 256;
            int row = idx >> 3, c4 = idx & 7;
            uint32_t part = (uint32_t)(row >> 7) * 16384u;
            uint32_t sw = SMEM_SWIZZLE_128B((uint32_t)((row & 127) * 128 + c4 * 16));
            cp_async16(st + part + sw, A + (size_t)(bm + row) * K + k0 + c4 * 4);
        }
        // B: 256 rows x 32 cols
#pragma unroll
        for (int t = 0; t < 8; t++) {
            int idx = tid + t * 256;
            int row = idx >> 3, c4 = idx & 7;
            uint32_t sw = SMEM_SWIZZLE_128B((uint32_t)(row * 128 + c4 * 16));
            cp_async16(st + 32768 + sw, Bm + (size_t)(bn + row) * K + k0 + c4 * 4);
        }
        CPASYNC_MBAR_ARRIVE_NOINC(m_full);

        if (wid == 0 && elect_one_pred()) {
            MBARRIER_WAIT_PARITY(m_full, i & 1);
            FENCE_PROXY_ASYNC_SHARED_CTA();
#pragma unroll
            for (int k = 0; k < 4; k++)
                TCGEN05_MMA_TF32_SS(tmem, dA0[s] + k * 2, dB[s] + k * 2,
                                    IDESC_128x256, (c > 0) || (k > 0));
#pragma unroll
            for (int k = 0; k < 4; k++)
                TCGEN05_MMA_TF32_SS(tmem + 256, dA1[s] + k * 2, dB[s] + k * 2,
                                    IDESC_128x256, (c > 0) || (k > 0));
            TCGEN05_COMMIT(m_emp);
        }
    }

    if (wid == 0 && elect_one_pred()) TCGEN05_COMMIT(m_done);
    MBARRIER_WAIT_PARITY(m_done, 0);
    TCGEN05_FENCE_AFTER();

    // Epilogue: warps 0-3 -> D0 (rows bm..bm+127), warps 4-7 -> D1 (+128)
    {
        const int lane = tid & 31;
        const int half = wid >> 2;                      // 0 or 1
        const int m = bm + half * 128 + (wid & 3) * 32 + lane;
        const uint32_t tbase = tmem + half * 256;
        float* crow = C + (size_t)m * N + bn;
#pragma unroll
        for (int g = 0; g < 8; g++) {
            uint32_t r[32];
            TCGEN05_LD_32X32B_X32(r, tbase + g * 32);
            TCGEN05_WAIT_LD();
            const int col0 = g * 32;
            if (mode == 2) {
#pragma unroll
                for (int j = 0; j < 32; j++) {
                    float v = __uint_as_float(r[j]) * scale;
                    if (s_mask[col0 + j] == 0) v = NEG_INF;
                    r[j] = __float_as_uint(v);
                }
            } else if (mode == 1) {
#pragma unroll
                for (int j = 0; j < 32; j++)
                    r[j] = __float_as_uint(__uint_as_float(r[j]) + s_bias[col0 + j]);
            } else {
#pragma unroll
                for (int j = 0; j < 32; j++)
                    r[j] = __float_as_uint(
                        to_tf32(__uint_as_float(r[j]) + s_bias[col0 + j]));
            }
#pragma unroll
            for (int j = 0; j < 8; j++)
                *(float4*)&crow[col0 + j * 4] = *(float4*)&r[j * 4];
        }
    }
    __syncthreads();
    if (wid == 0) TCGEN05_DEALLOC(tmem, 512);

#else
    // ---------------- SIMT fp32 fallback ----------------
    constexpr int BK = 16, TM = 8, TN = 8;
    constexpr int K2 = 256;
    float* As = (float*)smem;
    float* Bs = As + BK * 128;
    const int tx = tid & 15, ty = tid >> 4;

    for (int mh = 0; mh < 2; mh++) {
        const int bm2 = bm + mh * 128;
        for (int nh = 0; nh < 2; nh++) {
            const int bn2 = bn + nh * 128;
            float acc[TM][TN];
#pragma unroll
            for (int i = 0; i < TM; i++)
#pragma unroll
                for (int j = 0; j < TN; j++) acc[i][j] = 0.0f;

            for (int k0 = 0; k0 < K2; k0 += BK) {
                __syncthreads();
#pragma unroll
                for (int i = 0; i < 2; i++) {
                    int li = tid + i * 256;
                    int row = li >> 2, kc = (li & 3) << 2;
                    float4 va = *(const float4*)(A + (size_t)(bm2 + row) * K2 + k0 + kc);
                    As[(kc + 0) * 128 + row] = va.x; As[(kc + 1) * 128 + row] = va.y;
                    As[(kc + 2) * 128 + row] = va.z; As[(kc + 3) * 128 + row] = va.w;
                    float4 vb = *(const float4*)(Bm + (size_t)(bn2 + row) * K2 + k0 + kc);
                    Bs[(kc + 0) * 128 + row] = vb.x; Bs[(kc + 1) * 128 + row] = vb.y;
                    Bs[(kc + 2) * 128 + row] = vb.z; Bs[(kc + 3) * 128 + row] = vb.w;
                }
                __syncthreads();
#pragma unroll
                for (int kk = 0; kk < BK; kk++) {
                    float a[TM], bb[TN];
                    *(float4*)&a[0]  = *(const float4*)&As[kk * 128 + ty * TM];
                    *(float4*)&a[4]  = *(const float4*)&As[kk * 128 + ty * TM + 4];
                    *(float4*)&bb[0] = *(const float4*)&Bs[kk * 128 + tx * TN];
                    *(float4*)&bb[4] = *(const float4*)&Bs[kk * 128 + tx * TN + 4];
#pragma unroll
                    for (int i = 0; i < TM; i++)
#pragma unroll
                        for (int j = 0; j < TN; j++)
                            acc[i][j] = fmaf(a[i], bb[j], acc[i][j]);
                }
            }
            const int row0 = bm2 + ty * TM, col0 = bn2 + tx * TN;
#pragma unroll
            for (int i = 0; i < TM; i++)
#pragma unroll
                for (int j = 0; j < TN; j++) {
                    float v = acc[i][j];
                    size_t off = (size_t)(row0 + i) * N + col0 + j;
                    if (mode == 2) {
                        v *= scale;
                        if (mask[col0 + j] == 0) v = NEG_INF;
                        C[off] = v;
                    } else if (mode == 1) {
                        C[off] = v + bias[col0 + j];
                    } else {
                        C[off] = to_tf32(v + bias[col0 + j]);
                    }
                }
            __syncthreads();
        }
    }
#endif
}

// ---------------------------------------------------------------------------
// Softmax + column-sum, warp-per-row (no max subtraction; masked scores are
// -inf so exp gives exactly 0). Each warp handles 4 rows; its per-lane column
// partials (64 columns per lane) are written to a private wpart chunk.
// Block = 256 threads = 8 warps = 32 rows. Grid = (64, kB).
// ---------------------------------------------------------------------------
__global__ __launch_bounds__(256)
void softmax_colsum_kernel(const float* __restrict__ P, float* __restrict__ wpart)
{
    const int ch  = blockIdx.x;           // 0..63
    const int b   = blockIdx.y;
    const int wid = threadIdx.x >> 5;
    const int lane = threadIdx.x & 31;

    const int row0 = ch * 32 + wid * 4;   // 4 rows for this warp
    const float* base = P + ((size_t)b * kS + row0) * kS;

    float c[64];
#pragma unroll
    for (int j = 0; j < 64; j++) c[j] = 0.0f;

#pragma unroll
    for (int r = 0; r < 4; r++) {
        const float* p = base + (size_t)r * kS;
        float x[64];
        // lane's float4 stripe: f = lane + 32*j  (j<16) -> k = 4*lane + 128*j
#pragma unroll
        for (int j = 0; j < 16; j++)
            *(float4*)&x[j * 4] = *(const float4*)&p[(lane + j * 32) * 4];

        float s = 0.0f;
#pragma unroll
        for (int j = 0; j < 64; j++) {
            x[j] = __expf(x[j]);          // -inf -> 0
            s += x[j];
        }
#pragma unroll
        for (int o = 16; o; o >>= 1) s += __shfl_xor_sync(0xffffffffu, s, o);
        const float inv = 1.0f / s;
#pragma unroll
        for (int j = 0; j < 64; j++) c[j] = fmaf(x[j], inv, c[j]);
    }

    // chunk = global warp index within batch: ch*8 + wid  (0..511)
    float* o = wpart + ((size_t)(ch * 8 + wid) * kB + b) * kS;
#pragma unroll
    for (int j = 0; j < 16; j++)
        *(float4*)&o[(lane + j * 32) * 4] = *(float4*)&c[j * 4];
}

__global__ __launch_bounds__(256)
void colsum_reduce_kernel(const float* __restrict__ wpart, float* __restrict__ w)
{
    const int i = blockIdx.x * 256 + threadIdx.x;   // < kB*kS
    float s = 0.0f;
#pragma unroll 8
    for (int c = 0; c < WCH; c++) s += wpart[(size_t)c * (kB * kS) + i];
    w[i] = s;
}

__global__ __launch_bounds__(256)
void out_part_kernel(const float* __restrict__ w, const float* __restrict__ V,
                     float* __restrict__ opart)
{
    const int chunk = blockIdx.x;
    const int b     = blockIdx.y;
    const int d     = threadIdx.x;
    const float* vb = V + ((size_t)b * kS + (size_t)chunk * 64) * kD;
    const float* wb = w + b * kS + chunk * 64;
    float s = 0.0f;
#pragma unroll
    for (int k = 0; k < 64; k++) s = fmaf(wb[k], vb[(size_t)k * kD + d], s);
    opart[(size_t)(chunk * kB + b) * kD + d] = s;
}

__global__ __launch_bounds__(256)
void out_reduce_kernel(const float* __restrict__ opart, float* __restrict__ out)
{
    const int i = blockIdx.x * 256 + threadIdx.x;
    float s = 0.0f;
#pragma unroll
    for (int c = 0; c < N_KCHUNK; c++) s += opart[(size_t)c * (kB * kD) + i];
    out[i] = s * (1.0f / (float)kS);
}

// ---------------------------------------------------------------------------
// Launch
// ---------------------------------------------------------------------------
extern "C" void kernel_launch(void* const* d_in, const int* in_sizes, int n_in,
                              void* d_out, int out_size)
{
    const float* nodes = (const float*)d_in[0];
    const int*   mask  = (const int*)  d_in[1];
    const float* Wq    = (const float*)d_in[2];
    const float* bq    = (const float*)d_in[3];
    const float* Wk    = (const float*)d_in[4];
    const float* bk    = (const float*)d_in[5];
    const float* Wv    = (const float*)d_in[6];
    const float* bv    = (const float*)d_in[7];
    float* out = (float*)d_out;

    float *NR, *WqR, *WkR, *WvR, *Q, *K, *V, *P, *w, *wpart, *opart;
    cudaGetSymbolAddress((void**)&NR,  g_NR);
    cudaGetSymbolAddress((void**)&WqR, g_WqR);
    cudaGetSymbolAddress((void**)&WkR, g_WkR);
    cudaGetSymbolAddress((void**)&WvR, g_WvR);
    cudaGetSymbolAddress((void**)&Q,   g_Q);
    cudaGetSymbolAddress((void**)&K,   g_K);
    cudaGetSymbolAddress((void**)&V,   g_V);
    cudaGetSymbolAddress((void**)&P,   g_P);
    cudaGetSymbolAddress((void**)&w,   g_w);
    cudaGetSymbolAddress((void**)&wpart, g_wpart);
    cudaGetSymbolAddress((void**)&opart, g_opart);

    cudaFuncSetAttribute(pipe_gemm,
                         cudaFuncAttributeMaxDynamicSharedMemorySize, PG_SMEM);

    dim3 blk(256);

    // 1. Pre-round inputs to tf32 (rna)
    rnd_kernel<<<kM * kD / 256, blk>>>(nodes, NR);
    rnd_kernel<<<kD * kD / 256, blk>>>(Wq, WqR);
    rnd_kernel<<<kD * kD / 256, blk>>>(Wk, WkR);
    rnd_kernel<<<kD * kD / 256, blk>>>(Wv, WvR);

    // 2. Projections (single tf32, pipelined): BM=256, grid 64
    dim3 gproj(1, kM / 256, 1);
    pipe_gemm<<<gproj, blk, PG_SMEM>>>(NR, WqR, bq, nullptr, Q, kD, 0,
                                       0, 0, 0, 0, 1.0f);
    pipe_gemm<<<gproj, blk, PG_SMEM>>>(NR, WkR, bk, nullptr, K, kD, 0,
                                       0, 0, 0, 0, 1.0f);
    pipe_gemm<<<gproj, blk, PG_SMEM>>>(NR, WvR, bv, nullptr, V, kD, 1,
                                       0, 0, 0, 0, 1.0f);

    // 3. Scores: P = Q K^T / 16, mask -> -inf  (BM=256, BN=256)
    dim3 gsc(kS / 256, kS / 256, kB);
    pipe_gemm<<<gsc, blk, PG_SMEM>>>(Q, K, nullptr, mask, P, kS, 2,
                                     (long long)kS * kD,
                                     (long long)kS * kD,
                                     (long long)kS * kS, kS, 0.0625f);

    // 4. Softmax + column-sum, then the output contraction
    softmax_colsum_kernel<<<dim3(64, kB), blk>>>(P, wpart);
    colsum_reduce_kernel<<<(kB * kS) / 256, blk>>>(wpart, w);
    out_part_kernel<<<dim3(N_KCHUNK, kB), blk>>>(w, V, opart);
    out_reduce_kernel<<<(kB * kD) / 256, blk>>>(opart, out);
}

// round 7
// speedup vs baseline: 1.2159x; 1.2159x over previous
#include <cuda_runtime.h>
#include <cstdint>
#include <math.h>

// ---------------------------------------------------------------------------
// Problem constants
// ---------------------------------------------------------------------------
static constexpr int kB = 8;
static constexpr int kS = 2048;
static constexpr int kD = 256;
static constexpr int kM = kB * kS;
static constexpr int QCH = 64;       // softmax/colsum: 32 rows per chunk
static constexpr int N_KCHUNK = 32;  // output split over keys

// Scratch (static device memory)
// Q, K stored BLOCKED: block = [128 rows x 32 cols] = 16KB, SW128-swizzled.
// Block id = (global_mtile * 8 + kchunk), global_mtile = global_row / 128.
__device__ float g_Qb[kB * kS * kD];
__device__ float g_Kb[kB * kS * kD];
__device__ float g_V[kB * kS * kD];          // row-major fp32
__device__ float g_P[(size_t)kB * kS * kS];  // masked scaled scores
__device__ float g_w[kB * kS];
__device__ float g_wpart[QCH * kB * kS];
__device__ float g_opart[N_KCHUNK * kB * kD];

#if defined(__CUDA_ARCH__) && defined(__CUDA_ARCH_FEAT_SM103_ALL)
#define HAS_TCGEN05 1
#else
#define HAS_TCGEN05 0
#endif

#define SMEM_SWIZZLE_128B(byte_offset) \
    ((byte_offset) ^ (((byte_offset) >> 3) & 0x70))

__device__ __forceinline__ uint32_t smem_to_u32_gen(const void* p) {
    uint32_t a;
    asm("{ .reg .u64 t; cvta.to.shared.u64 t, %1; cvt.u32.u64 %0, t; }"
        : "=r"(a) : "l"(p));
    return a;
}

__device__ __forceinline__ float to_tf32(float x) {
    float y;
    asm("cvt.rna.tf32.f32 %0, %1;" : "=f"(y) : "f"(x));
    return y;
}

// float-index offset of element (row m in [0,128), col c in [0,32)) inside a
// 16KB swizzled block, plus block addressing helper.
__device__ __forceinline__ size_t qk_blk_off(int gmtile, int kchunk, int r, int c) {
    uint32_t byte = (uint32_t)(r * 128 + (c >> 2) * 16);
    uint32_t sw = SMEM_SWIZZLE_128B(byte) + (uint32_t)(c & 3) * 4;
    return ((size_t)(gmtile * 8 + kchunk) << 12) + (sw >> 2);
}

#if HAS_TCGEN05
__device__ __forceinline__ uint32_t elect_one_pred() {
    uint32_t pred;
    asm volatile(
        "{\n\t.reg .pred p;\n\t"
        "elect.sync _|p, 0xFFFFFFFF;\n\t"
        "selp.b32 %0, 1, 0, p;\n\t}"
        : "=r"(pred));
    return pred;
}

#define TCGEN05_ALLOC(smem_result_addr, nCols) \
    asm volatile("tcgen05.alloc.cta_group::1.sync.aligned.shared::cta.b32 [%0], %1;" \
                 :: "r"((uint32_t)(smem_result_addr)), "r"((uint32_t)(nCols)) : "memory")
#define TCGEN05_DEALLOC(tmem_addr, nCols) \
    asm volatile("tcgen05.dealloc.cta_group::1.sync.aligned.b32 %0, %1;" \
                 :: "r"(tmem_addr), "r"((uint32_t)(nCols)))
#define TCGEN05_RELINQUISH() \
    asm volatile("tcgen05.relinquish_alloc_permit.cta_group::1.sync.aligned;")
#define TCGEN05_COMMIT(mbar_smem_addr) \
    asm volatile("tcgen05.commit.cta_group::1.mbarrier::arrive::one.shared::cluster.b64 [%0];" \
                 :: "r"((uint32_t)(mbar_smem_addr)) : "memory")
#define TCGEN05_FENCE_AFTER() \
    asm volatile("tcgen05.fence::after_thread_sync;" ::: "memory")
#define TCGEN05_WAIT_LD() \
    asm volatile("tcgen05.wait::ld.sync.aligned;" ::: "memory")
#define MBARRIER_INIT(mbar_smem_addr, count) \
    asm volatile("mbarrier.init.shared.b64 [%0], %1;" \
                 :: "r"((uint32_t)(mbar_smem_addr)), "r"((uint32_t)(count)) : "memory")
#define MBARRIER_EXPECT_TX(mbar_smem_addr, tx_bytes) \
    asm volatile("mbarrier.arrive.expect_tx.shared.b64 _, [%0], %1;" \
                 :: "r"((uint32_t)(mbar_smem_addr)), "r"((uint32_t)(tx_bytes)) : "memory")
#define FENCE_PROXY_ASYNC_SHARED_CTA() \
    asm volatile("fence.proxy.async.shared::cta;" ::: "memory")

#define MBARRIER_WAIT_PARITY(mbar_smem_addr, phase_parity) do { \
    uint32_t _mbar = (uint32_t)(mbar_smem_addr); \
    uint32_t _parity = (uint32_t)(phase_parity); \
    uint32_t _done; \
    asm volatile( \
        "{\n\t.reg .pred p;\n\t" \
        "mbarrier.try_wait.parity.acquire.cta.shared::cta.b64 p, [%1], %2;\n\t" \
        "selp.b32 %0, 1, 0, p;\n\t}" \
        : "=r"(_done) : "r"(_mbar), "r"(_parity) : "memory"); \
    if (!_done) { \
        asm volatile( \
            "{\n\t.reg .pred P1;\n\t" \
            "WAIT_LOOP_%=:\n\t" \
            "mbarrier.try_wait.parity.acquire.cta.shared::cta.b64 P1, [%0], %1, 0x989680;\n\t" \
            "@P1 bra.uni WAIT_DONE_%=;\n\t" \
            "bra.uni WAIT_LOOP_%=;\n\t" \
            "WAIT_DONE_%=:\n\t}" \
            :: "r"(_mbar), "r"(_parity) : "memory"); \
    } \
} while(0)

#define TCGEN05_LD_32X32B_X32(r, tmem_addr) \
    asm volatile( \
        "tcgen05.ld.sync.aligned.32x32b.x32.b32 " \
        "{%0, %1, %2, %3, %4, %5, %6, %7, " \
        " %8, %9, %10, %11, %12, %13, %14, %15, " \
        " %16, %17, %18, %19, %20, %21, %22, %23, " \
        " %24, %25, %26, %27, %28, %29, %30, %31}, [%32];" \
        : "=r"((r)[0]),  "=r"((r)[1]),  "=r"((r)[2]),  "=r"((r)[3]), \
          "=r"((r)[4]),  "=r"((r)[5]),  "=r"((r)[6]),  "=r"((r)[7]), \
          "=r"((r)[8]),  "=r"((r)[9]),  "=r"((r)[10]), "=r"((r)[11]), \
          "=r"((r)[12]), "=r"((r)[13]), "=r"((r)[14]), "=r"((r)[15]), \
          "=r"((r)[16]), "=r"((r)[17]), "=r"((r)[18]), "=r"((r)[19]), \
          "=r"((r)[20]), "=r"((r)[21]), "=r"((r)[22]), "=r"((r)[23]), \
          "=r"((r)[24]), "=r"((r)[25]), "=r"((r)[26]), "=r"((r)[27]), \
          "=r"((r)[28]), "=r"((r)[29]), "=r"((r)[30]), "=r"((r)[31]) \
        : "r"(tmem_addr))

#define TCGEN05_MMA_TF32_SS(d_tmem, a_desc, b_desc, idesc, enable_d) do { \
    uint32_t _en = (enable_d) ? 1u : 0u; \
    uint32_t _zero = 0u; \
    asm volatile( \
        "{\n\t.reg .pred p;\n\t" \
        "setp.ne.u32 p, %5, 0;\n\t" \
        "tcgen05.mma.cta_group::1.kind::tf32 [%0], %1, %2, %3, {%4, %4, %4, %4}, p;\n\t" \
        "}" \
        :: "r"(d_tmem), "l"(a_desc), "l"(b_desc), "r"(idesc), "r"(_zero), "r"(_en) \
        : "memory"); \
} while(0)

static constexpr uint64_t SMEM_DESC_BASE_SW128 =
    (uint64_t(2)  << 61) | (uint64_t(1) << 46) | (uint64_t(64) << 32) | (uint64_t(1) << 16);
#define MAKE_SMEM_DESC(base_addr) \
    (SMEM_DESC_BASE_SW128 | ((uint64_t)((base_addr) >> 4) & 0x3FFF))

#define CP_ASYNC_BULK(dst_smem, src_gmem, bytes, mbar) \
    asm volatile("cp.async.bulk.shared::cta.global.mbarrier::complete_tx::bytes " \
                 "[%0], [%1], %2, [%3];" \
                 :: "r"((uint32_t)(dst_smem)), "l"(src_gmem), \
                    "r"((uint32_t)(bytes)), "r"((uint32_t)(mbar)) : "memory")

// IDESC for tf32, F32 accum, M=128, N=256
static constexpr uint32_t IDESC_128x256 =
    (1u << 4) | (2u << 7) | (2u << 10) | ((256 / 8) << 17) | ((128 / 16) << 24);
#endif  // HAS_TCGEN05

// ---------------------------------------------------------------------------
// Projection GEMM (3xTF32, sync staging): C[m,n] = sum_k A[m,k]*B[n,k] + bias
// BM=128, BN=256, K=256 in 8 chunks of 32.
// mode 0: tf32-rounded output, written to BLOCKED layout (Q, K)
// mode 1: plain fp32 row-major (V)
// smem: [0,8) mbar, [8,12) tmem, [64,1088) bias,
//       [4096..) Ah 16K | Al 16K | Bh 32K | Bl 32K
// ---------------------------------------------------------------------------
static constexpr int PROJ_SMEM = 4096 + 98304;

__global__ __launch_bounds__(256)
void proj_gemm(const float* __restrict__ A, const float* __restrict__ Bm,
               const float* __restrict__ bias, float* __restrict__ C, int mode)
{
    extern __shared__ __align__(1024) char smem[];
    const int tid = threadIdx.x;
    const int bm = blockIdx.y * 128;
    constexpr int N = 256, K = 256;

#if HAS_TCGEN05
    const uint32_t sb = smem_to_u32_gen(smem);
    const uint32_t mbar = sb;
    float* s_bias = (float*)(smem + 64);
    const int wid = tid >> 5;

    if (wid == 0) { TCGEN05_ALLOC(sb + 8, 256); TCGEN05_RELINQUISH(); }
    if (tid == 0) MBARRIER_INIT(mbar, 1);
    s_bias[tid] = bias[tid];
    __syncthreads();
    const uint32_t tmem = *(volatile uint32_t*)(smem + 8);

    const uint32_t tAh = sb + 4096;
    const uint32_t tAl = tAh + 16384;
    const uint32_t tBh = tAl + 16384;
    const uint32_t tBl = tBh + 32768;
    const uint64_t dAh = MAKE_SMEM_DESC(tAh);
    const uint64_t dAl = MAKE_SMEM_DESC(tAl);
    const uint64_t dBh = MAKE_SMEM_DESC(tBh);
    const uint64_t dBl = MAKE_SMEM_DESC(tBl);

    for (int c = 0; c < K / 32; c++) {
        const int k0 = c * 32;
        __syncthreads();
#pragma unroll
        for (int t = 0; t < 4; t++) {
            int idx = tid + t * 256;
            int row = idx >> 3, c4 = idx & 7;
            uint32_t sw = SMEM_SWIZZLE_128B((uint32_t)(row * 128 + c4 * 16));
            float4 v = *(const float4*)(A + (size_t)(bm + row) * K + k0 + c4 * 4);
            float4 h, l;
            h.x = to_tf32(v.x); l.x = to_tf32(v.x - h.x);
            h.y = to_tf32(v.y); l.y = to_tf32(v.y - h.y);
            h.z = to_tf32(v.z); l.z = to_tf32(v.z - h.z);
            h.w = to_tf32(v.w); l.w = to_tf32(v.w - h.w);
            *(float4*)(smem + (tAh - sb) + sw) = h;
            *(float4*)(smem + (tAl - sb) + sw) = l;
        }
#pragma unroll
        for (int t = 0; t < 8; t++) {
            int idx = tid + t * 256;
            int row = idx >> 3, c4 = idx & 7;
            uint32_t sw = SMEM_SWIZZLE_128B((uint32_t)(row * 128 + c4 * 16));
            float4 v = *(const float4*)(Bm + (size_t)row * K + k0 + c4 * 4);
            float4 h, l;
            h.x = to_tf32(v.x); l.x = to_tf32(v.x - h.x);
            h.y = to_tf32(v.y); l.y = to_tf32(v.y - h.y);
            h.z = to_tf32(v.z); l.z = to_tf32(v.z - h.z);
            h.w = to_tf32(v.w); l.w = to_tf32(v.w - h.w);
            *(float4*)(smem + (tBh - sb) + sw) = h;
            *(float4*)(smem + (tBl - sb) + sw) = l;
        }
        FENCE_PROXY_ASYNC_SHARED_CTA();
        __syncthreads();

        if (wid == 0 && elect_one_pred()) {
#pragma unroll
            for (int k = 0; k < 4; k++)
                TCGEN05_MMA_TF32_SS(tmem, dAh + k * 2, dBh + k * 2, IDESC_128x256,
                                    (c > 0) || (k > 0));
#pragma unroll
            for (int k = 0; k < 4; k++)
                TCGEN05_MMA_TF32_SS(tmem, dAh + k * 2, dBl + k * 2, IDESC_128x256, true);
#pragma unroll
            for (int k = 0; k < 4; k++)
                TCGEN05_MMA_TF32_SS(tmem, dAl + k * 2, dBh + k * 2, IDESC_128x256, true);
            TCGEN05_COMMIT(mbar);
        }
        MBARRIER_WAIT_PARITY(mbar, c & 1);
    }

    TCGEN05_FENCE_AFTER();

    if (wid < 4) {
        const int lane = tid & 31;
        const int mloc = wid * 32 + lane;          // row within 128-tile
        const int m = bm + mloc;                   // global row
#pragma unroll
        for (int g = 0; g < 8; g++) {
            uint32_t r[32];
            TCGEN05_LD_32X32B_X32(r, tmem + g * 32);
            TCGEN05_WAIT_LD();
            const int col0 = g * 32;
            if (mode == 0) {
                // tf32-round, write into blocked-swizzled layout.
                // Block = (m/128)*8 + g; inside: swizzled (mloc*128 + j*16).
#pragma unroll
                for (int j = 0; j < 32; j++)
                    r[j] = __float_as_uint(
                        to_tf32(__uint_as_float(r[j]) + s_bias[col0 + j]));
                float* blk = C + (((size_t)(m >> 7) * 8 + g) << 12);
#pragma unroll
                for (int j = 0; j < 8; j++) {
                    uint32_t sw = SMEM_SWIZZLE_128B((uint32_t)(mloc * 128 + j * 16));
                    *(float4*)((char*)blk + sw) = *(float4*)&r[j * 4];
                }
            } else {
#pragma unroll
                for (int j = 0; j < 32; j++)
                    r[j] = __float_as_uint(__uint_as_float(r[j]) + s_bias[col0 + j]);
                float* crow = C + (size_t)m * N;
#pragma unroll
                for (int j = 0; j < 8; j++)
                    *(float4*)&crow[col0 + j * 4] = *(float4*)&r[j * 4];
            }
        }
    }
    __syncthreads();
    if (wid == 0) TCGEN05_DEALLOC(tmem, 256);

#else
    // SIMT fallback
    constexpr int BK = 16, TM = 8, TN = 8;
    float* As = (float*)smem;
    float* Bs = As + BK * 128;
    const int tx = tid & 15, ty = tid >> 4;

    for (int nh = 0; nh < 2; nh++) {
        const int bn2 = nh * 128;
        float acc[TM][TN];
#pragma unroll
        for (int i = 0; i < TM; i++)
#pragma unroll
            for (int j = 0; j < TN; j++) acc[i][j] = 0.0f;

        for (int k0 = 0; k0 < K; k0 += BK) {
            __syncthreads();
#pragma unroll
            for (int i = 0; i < 2; i++) {
                int li = tid + i * 256;
                int row = li >> 2, kc = (li & 3) << 2;
                float4 va = *(const float4*)(A + (size_t)(bm + row) * K + k0 + kc);
                As[(kc + 0) * 128 + row] = va.x; As[(kc + 1) * 128 + row] = va.y;
                As[(kc + 2) * 128 + row] = va.z; As[(kc + 3) * 128 + row] = va.w;
                float4 vb = *(const float4*)(Bm + (size_t)(bn2 + row) * K + k0 + kc);
                Bs[(kc + 0) * 128 + row] = vb.x; Bs[(kc + 1) * 128 + row] = vb.y;
                Bs[(kc + 2) * 128 + row] = vb.z; Bs[(kc + 3) * 128 + row] = vb.w;
            }
            __syncthreads();
#pragma unroll
            for (int kk = 0; kk < BK; kk++) {
                float a[TM], bb[TN];
                *(float4*)&a[0]  = *(const float4*)&As[kk * 128 + ty * TM];
                *(float4*)&a[4]  = *(const float4*)&As[kk * 128 + ty * TM + 4];
                *(float4*)&bb[0] = *(const float4*)&Bs[kk * 128 + tx * TN];
                *(float4*)&bb[4] = *(const float4*)&Bs[kk * 128 + tx * TN + 4];
#pragma unroll
                for (int i = 0; i < TM; i++)
#pragma unroll
                    for (int j = 0; j < TN; j++)
                        acc[i][j] = fmaf(a[i], bb[j], acc[i][j]);
            }
        }
        const int row0 = bm + ty * TM, col0 = bn2 + tx * TN;
#pragma unroll
        for (int i = 0; i < TM; i++)
#pragma unroll
            for (int j = 0; j < TN; j++) {
                float v = acc[i][j] + bias[col0 + j];
                int m = row0 + i, n = col0 + j;
                if (mode == 0)
                    C[qk_blk_off(m >> 7, n >> 5, m & 127, n & 31)] = to_tf32(v);
                else
                    C[(size_t)m * N + n] = v;
            }
        __syncthreads();
    }
#endif
}

// ---------------------------------------------------------------------------
// Scores GEMM (single tf32, cp.async.bulk 2-stage pipeline):
//   P[b,m,n] = (Q[b,m,:] . K[b,n,:]) * scale, masked n -> -inf
// BM=128, BN=256, K=256 in 8 chunks of 32. Q,K in blocked-swizzled layout,
// each chunk staged with 3 bulk copies (A 16K, B 2x16K).
// smem: [0,8) full0 [8,16) full1 [16,24) emp0 [24,32) emp1 [32,40) done
//       [40,44) tmem, [64,1088) mask[256]
//       [4096..) stage0 {A 16K | B 32K}, stage1 {A 16K | B 32K}
// ---------------------------------------------------------------------------
static constexpr int SC_STAGE = 49152;
static constexpr int SC_SMEM = 4096 + 2 * SC_STAGE;

__global__ __launch_bounds__(256)
void score_gemm(const float* __restrict__ Qb, const float* __restrict__ Kb,
                const int* __restrict__ mask, float* __restrict__ P, float scale)
{
    extern __shared__ __align__(1024) char smem[];
    const int tid = threadIdx.x;
    const int bz = blockIdx.z;
    float* C = P + (size_t)bz * kS * kS;
    const int* mk = mask + (size_t)bz * kS;

    const int my = blockIdx.y;          // m tile (128 rows) within batch
    const int nx = blockIdx.x;          // n tile (256 cols) within batch
    const int bm = my * 128;
    const int bn = nx * 256;
    const float NEG_INF = __int_as_float(0xff800000u);

#if HAS_TCGEN05
    const uint32_t sb = smem_to_u32_gen(smem);
    const uint32_t m_full0 = sb + 0,  m_full1 = sb + 8;
    const uint32_t m_emp0  = sb + 16, m_emp1  = sb + 24;
    const uint32_t m_done  = sb + 32;
    int* s_mask = (int*)(smem + 64);
    const int wid = tid >> 5;

    if (wid == 0) { TCGEN05_ALLOC(sb + 40, 256); TCGEN05_RELINQUISH(); }
    if (tid == 0) {
        MBARRIER_INIT(m_full0, 1);
        MBARRIER_INIT(m_full1, 1);
        MBARRIER_INIT(m_emp0, 1);
        MBARRIER_INIT(m_emp1, 1);
        MBARRIER_INIT(m_done, 1);
    }
    s_mask[tid] = mk[bn + tid];
    __syncthreads();
    const uint32_t tmem = *(volatile uint32_t*)(smem + 40);

    uint64_t dA[2], dB[2];
#pragma unroll
    for (int s = 0; s < 2; s++) {
        uint32_t base = sb + 4096 + s * SC_STAGE;
        dA[s] = MAKE_SMEM_DESC(base);
        dB[s] = MAKE_SMEM_DESC(base + 16384);
    }

    // base block indices for this batch
    const int amt = bz * 16 + my;            // A global mtile
    const int bmt0 = bz * 16 + nx * 2;       // B global mtiles (2 of them)

    if (wid == 1) {
        // producer warp: one elected thread issues expect_tx + 3 bulk copies
        if (elect_one_pred()) {
            for (int c = 0; c < 8; c++) {
                const int s = c & 1;
                const int i = c >> 1;
                const uint32_t m_full = s ? m_full1 : m_full0;
                const uint32_t m_emp  = s ? m_emp1  : m_emp0;
                const uint32_t st = sb + 4096 + s * SC_STAGE;
                MBARRIER_WAIT_PARITY(m_emp, 1 ^ (i & 1));
                MBARRIER_EXPECT_TX(m_full, SC_STAGE);
                CP_ASYNC_BULK(st,
                              Qb + (((size_t)amt * 8 + c) << 12), 16384, m_full);
                CP_ASYNC_BULK(st + 16384,
                              Kb + (((size_t)bmt0 * 8 + c) << 12), 16384, m_full);
                CP_ASYNC_BULK(st + 32768,
                              Kb + (((size_t)(bmt0 + 1) * 8 + c) << 12), 16384, m_full);
            }
        }
    } else if (wid == 0) {
        // consumer: elected thread issues the MMAs
        if (elect_one_pred()) {
            for (int c = 0; c < 8; c++) {
                const int s = c & 1;
                const int i = c >> 1;
                const uint32_t m_full = s ? m_full1 : m_full0;
                const uint32_t m_emp  = s ? m_emp1  : m_emp0;
                MBARRIER_WAIT_PARITY(m_full, i & 1);
#pragma unroll
                for (int k = 0; k < 4; k++)
                    TCGEN05_MMA_TF32_SS(tmem, dA[s] + k * 2, dB[s] + k * 2,
                                        IDESC_128x256, (c > 0) || (k > 0));
                TCGEN05_COMMIT(m_emp);
            }
            TCGEN05_COMMIT(m_done);
        }
    }

    MBARRIER_WAIT_PARITY(m_done, 0);
    TCGEN05_FENCE_AFTER();

    if (wid < 4) {
        const int m = bm + wid * 32 + (tid & 31);
        float* crow = C + (size_t)m * kS + bn;
#pragma unroll
        for (int g = 0; g < 8; g++) {
            uint32_t r[32];
            TCGEN05_LD_32X32B_X32(r, tmem + g * 32);
            TCGEN05_WAIT_LD();
            const int col0 = g * 32;
#pragma unroll
            for (int j = 0; j < 32; j++) {
                float v = __uint_as_float(r[j]) * scale;
                if (s_mask[col0 + j] == 0) v = NEG_INF;
                r[j] = __float_as_uint(v);
            }
#pragma unroll
            for (int j = 0; j < 8; j++)
                *(float4*)&crow[col0 + j * 4] = *(float4*)&r[j * 4];
        }
    }
    __syncthreads();
    if (wid == 0) TCGEN05_DEALLOC(tmem, 256);

#else
    // SIMT fallback — reads blocked Q/K layout
    constexpr int BK = 16, TM = 8, TN = 8;
    float* As = (float*)smem;
    float* Bs = As + BK * 128;
    const int tx = tid & 15, ty = tid >> 4;
    const int amt = bz * 16 + my;
    const int bmt0 = bz * 16 + nx * 2;

    for (int nh = 0; nh < 2; nh++) {
        const int bmtl = bmt0 + nh;
        float acc[TM][TN];
#pragma unroll
        for (int i = 0; i < TM; i++)
#pragma unroll
            for (int j = 0; j < TN; j++) acc[i][j] = 0.0f;

        for (int k0 = 0; k0 < kD; k0 += BK) {
            __syncthreads();
            for (int li = tid; li < 128 * BK; li += 256) {
                int row = li / BK, kc = li % BK;
                As[kc * 128 + row] =
                    Qb[qk_blk_off(amt, (k0 + kc) >> 5, row, (k0 + kc) & 31)];
                Bs[kc * 128 + row] =
                    Kb[qk_blk_off(bmtl, (k0 + kc) >> 5, row, (k0 + kc) & 31)];
            }
            __syncthreads();
#pragma unroll
            for (int kk = 0; kk < BK; kk++) {
                float a[TM], bb[TN];
                *(float4*)&a[0]  = *(const float4*)&As[kk * 128 + ty * TM];
                *(float4*)&a[4]  = *(const float4*)&As[kk * 128 + ty * TM + 4];
                *(float4*)&bb[0] = *(const float4*)&Bs[kk * 128 + tx * TN];
                *(float4*)&bb[4] = *(const float4*)&Bs[kk * 128 + tx * TN + 4];
#pragma unroll
                for (int i = 0; i < TM; i++)
#pragma unroll
                    for (int j = 0; j < TN; j++)
                        acc[i][j] = fmaf(a[i], bb[j], acc[i][j]);
            }
        }
        const int row0 = bm + ty * TM, col0 = nh * 128 + bn + tx * TN;
#pragma unroll
        for (int i = 0; i < TM; i++)
#pragma unroll
            for (int j = 0; j < TN; j++) {
                float v = acc[i][j] * scale;
                if (mk[col0 + j] == 0) v = NEG_INF;
                C[(size_t)(row0 + i) * kS + col0 + j] = v;
            }
        __syncthreads();
    }
#endif
}

// ---------------------------------------------------------------------------
// Block reductions
// ---------------------------------------------------------------------------
__device__ __forceinline__ float block_reduce_max(float v)
{
    __shared__ float sm[8];
    for (int o = 16; o; o >>= 1) v = fmaxf(v, __shfl_xor_sync(0xffffffffu, v, o));
    if ((threadIdx.x & 31) == 0) sm[threadIdx.x >> 5] = v;
    __syncthreads();
    if (threadIdx.x < 32) {
        v = sm[threadIdx.x & 7];
        for (int o = 4; o; o >>= 1) v = fmaxf(v, __shfl_xor_sync(0xffffffffu, v, o));
        if (threadIdx.x == 0) sm[0] = v;
    }
    __syncthreads();
    float r = sm[0];
    __syncthreads();
    return r;
}

__device__ __forceinline__ float block_reduce_sum(float v)
{
    __shared__ float sm[8];
    for (int o = 16; o; o >>= 1) v += __shfl_xor_sync(0xffffffffu, v, o);
    if ((threadIdx.x & 31) == 0) sm[threadIdx.x >> 5] = v;
    __syncthreads();
    if (threadIdx.x < 32) {
        v = sm[threadIdx.x & 7];
        for (int o = 4; o; o >>= 1) v += __shfl_xor_sync(0xffffffffu, v, o);
        if (threadIdx.x == 0) sm[0] = v;
    }
    __syncthreads();
    float r = sm[0];
    __syncthreads();
    return r;
}

// ---------------------------------------------------------------------------
// Fused softmax + column-sum (no prob materialization) — R5 version
// ---------------------------------------------------------------------------
__global__ __launch_bounds__(256)
void softmax_colsum_kernel(const float* __restrict__ P, float* __restrict__ wpart)
{
    const int ch = blockIdx.x;
    const int b  = blockIdx.y;
    const int tid = threadIdx.x;
    const float* base = P + ((size_t)b * kS + (size_t)ch * 32) * kS;

    float wacc[8];
#pragma unroll
    for (int i = 0; i < 8; i++) wacc[i] = 0.0f;

    for (int r = 0; r < 32; r++) {
        const float* p = base + (size_t)r * kS + tid * 8;
        float x[8];
        *(float4*)&x[0] = *(const float4*)&p[0];
        *(float4*)&x[4] = *(const float4*)&p[4];

        float m = x[0];
#pragma unroll
        for (int i = 1; i < 8; i++) m = fmaxf(m, x[i]);
        m = block_reduce_max(m);

        float e[8], s = 0.0f;
#pragma unroll
        for (int i = 0; i < 8; i++) {
            e[i] = __expf(x[i] - m);
            s += e[i];
        }
        s = block_reduce_sum(s);
        const float inv = 1.0f / s;
#pragma unroll
        for (int i = 0; i < 8; i++) wacc[i] = fmaf(e[i], inv, wacc[i]);
    }

    float* o = wpart + (size_t)ch * (kB * kS) + (size_t)b * kS + tid * 8;
    *(float4*)&o[0] = make_float4(wacc[0], wacc[1], wacc[2], wacc[3]);
    *(float4*)&o[4] = make_float4(wacc[4], wacc[5], wacc[6], wacc[7]);
}

__global__ __launch_bounds__(256)
void colsum_reduce_kernel(const float* __restrict__ wpart, float* __restrict__ w)
{
    const int i = blockIdx.x * 256 + threadIdx.x;
    float s = 0.0f;
#pragma unroll
    for (int c = 0; c < QCH; c++) s += wpart[(size_t)c * (kB * kS) + i];
    w[i] = s;
}

__global__ __launch_bounds__(256)
void out_part_kernel(const float* __restrict__ w, const float* __restrict__ V,
                     float* __restrict__ opart)
{
    const int chunk = blockIdx.x;
    const int b     = blockIdx.y;
    const int d     = threadIdx.x;
    const float* vb = V + ((size_t)b * kS + (size_t)chunk * 64) * kD;
    const float* wb = w + b * kS + chunk * 64;
    float s = 0.0f;
#pragma unroll
    for (int k = 0; k < 64; k++) s = fmaf(wb[k], vb[(size_t)k * kD + d], s);
    opart[(size_t)(chunk * kB + b) * kD + d] = s;
}

__global__ __launch_bounds__(256)
void out_reduce_kernel(const float* __restrict__ opart, float* __restrict__ out)
{
    const int i = blockIdx.x * 256 + threadIdx.x;
    float s = 0.0f;
#pragma unroll
    for (int c = 0; c < N_KCHUNK; c++) s += opart[(size_t)c * (kB * kD) + i];
    out[i] = s * (1.0f / (float)kS);
}

// ---------------------------------------------------------------------------
// Launch
// ---------------------------------------------------------------------------
extern "C" void kernel_launch(void* const* d_in, const int* in_sizes, int n_in,
                              void* d_out, int out_size)
{
    const float* nodes = (const float*)d_in[0];
    const int*   mask  = (const int*)  d_in[1];
    const float* Wq    = (const float*)d_in[2];
    const float* bq    = (const float*)d_in[3];
    const float* Wk    = (const float*)d_in[4];
    const float* bk    = (const float*)d_in[5];
    const float* Wv    = (const float*)d_in[6];
    const float* bv    = (const float*)d_in[7];
    float* out = (float*)d_out;

    float *Qb, *Kb, *V, *P, *w, *wpart, *opart;
    cudaGetSymbolAddress((void**)&Qb,    g_Qb);
    cudaGetSymbolAddress((void**)&Kb,    g_Kb);
    cudaGetSymbolAddress((void**)&V,     g_V);
    cudaGetSymbolAddress((void**)&P,     g_P);
    cudaGetSymbolAddress((void**)&w,     g_w);
    cudaGetSymbolAddress((void**)&wpart, g_wpart);
    cudaGetSymbolAddress((void**)&opart, g_opart);

    cudaFuncSetAttribute(proj_gemm,
                         cudaFuncAttributeMaxDynamicSharedMemorySize, PROJ_SMEM);
    cudaFuncSetAttribute(score_gemm,
                         cudaFuncAttributeMaxDynamicSharedMemorySize, SC_SMEM);

    dim3 blk(256);

    // 1. Projections (3xTF32). Q,K -> blocked tf32; V -> row-major fp32.
    dim3 gproj(1, kM / 128, 1);
    proj_gemm<<<gproj, blk, PROJ_SMEM>>>(nodes, Wq, bq, Qb, 0);
    proj_gemm<<<gproj, blk, PROJ_SMEM>>>(nodes, Wk, bk, Kb, 0);
    proj_gemm<<<gproj, blk, PROJ_SMEM>>>(nodes, Wv, bv, V, 1);

    // 2. Scores (single tf32, bulk-copy pipelined): P = Q K^T / 16
    dim3 gsc(kS / 256, kS / 128, kB);
    score_gemm<<<gsc, blk, SC_SMEM>>>(Qb, Kb, mask, P, 0.0625f);

    // 3. Fused softmax + column-sum, then the output contraction
    softmax_colsum_kernel<<<dim3(QCH, kB), blk>>>(P, wpart);
    colsum_reduce_kernel<<<(kB * kS) / 256, blk>>>(wpart, w);
    out_part_kernel<<<dim3(N_KCHUNK, kB), blk>>>(w, V, opart);
    out_reduce_kernel<<<(kB * kD) / 256, blk>>>(opart, out);
}

// round 8
// speedup vs baseline: 1.3482x; 1.1088x over previous
#include <cuda_runtime.h>
#include <cstdint>
#include <math.h>

// ---------------------------------------------------------------------------
// Problem constants
// ---------------------------------------------------------------------------
static constexpr int kB = 8;
static constexpr int kS = 2048;
static constexpr int kD = 256;
static constexpr int kM = kB * kS;
static constexpr int QCH = 64;       // colsum: 32 rows per chunk
static constexpr int N_KCHUNK = 32;  // output split over keys
static constexpr int NXT = kS / 256; // 8 n-tiles per batch row

// Scratch (static device memory)
// Q, K stored BLOCKED: block = [128 rows x 32 cols] = 16KB, SW128-swizzled.
__device__ float g_Qb[kB * kS * kD];
__device__ float g_Kb[kB * kS * kD];
__device__ float g_V[kB * kS * kD];          // row-major fp32
__device__ float g_P[(size_t)kB * kS * kS];  // E = exp(score/16), masked -> 0
__device__ float g_rpart[NXT * kB * kS];     // row-sum partials
__device__ float g_invr[kB * kS];            // 1 / rowsum
__device__ float g_w[kB * kS];
__device__ float g_wpart[QCH * kB * kS];
__device__ float g_opart[N_KCHUNK * kB * kD];

#if defined(__CUDA_ARCH__) && defined(__CUDA_ARCH_FEAT_SM103_ALL)
#define HAS_TCGEN05 1
#else
#define HAS_TCGEN05 0
#endif

#define SMEM_SWIZZLE_128B(byte_offset) \
    ((byte_offset) ^ (((byte_offset) >> 3) & 0x70))

__device__ __forceinline__ uint32_t smem_to_u32_gen(const void* p) {
    uint32_t a;
    asm("{ .reg .u64 t; cvta.to.shared.u64 t, %1; cvt.u32.u64 %0, t; }"
        : "=r"(a) : "l"(p));
    return a;
}

__device__ __forceinline__ float to_tf32(float x) {
    float y;
    asm("cvt.rna.tf32.f32 %0, %1;" : "=f"(y) : "f"(x));
    return y;
}

// float-index offset of element (row m in [0,128), col c in [0,32)) inside a
// 16KB swizzled block.
__device__ __forceinline__ size_t qk_blk_off(int gmtile, int kchunk, int r, int c) {
    uint32_t byte = (uint32_t)(r * 128 + (c >> 2) * 16);
    uint32_t sw = SMEM_SWIZZLE_128B(byte) + (uint32_t)(c & 3) * 4;
    return ((size_t)(gmtile * 8 + kchunk) << 12) + (sw >> 2);
}

#if HAS_TCGEN05
__device__ __forceinline__ uint32_t elect_one_pred() {
    uint32_t pred;
    asm volatile(
        "{\n\t.reg .pred p;\n\t"
        "elect.sync _|p, 0xFFFFFFFF;\n\t"
        "selp.b32 %0, 1, 0, p;\n\t}"
        : "=r"(pred));
    return pred;
}

#define TCGEN05_ALLOC(smem_result_addr, nCols) \
    asm volatile("tcgen05.alloc.cta_group::1.sync.aligned.shared::cta.b32 [%0], %1;" \
                 :: "r"((uint32_t)(smem_result_addr)), "r"((uint32_t)(nCols)) : "memory")
#define TCGEN05_DEALLOC(tmem_addr, nCols) \
    asm volatile("tcgen05.dealloc.cta_group::1.sync.aligned.b32 %0, %1;" \
                 :: "r"(tmem_addr), "r"((uint32_t)(nCols)))
#define TCGEN05_RELINQUISH() \
    asm volatile("tcgen05.relinquish_alloc_permit.cta_group::1.sync.aligned;")
#define TCGEN05_COMMIT(mbar_smem_addr) \
    asm volatile("tcgen05.commit.cta_group::1.mbarrier::arrive::one.shared::cluster.b64 [%0];" \
                 :: "r"((uint32_t)(mbar_smem_addr)) : "memory")
#define TCGEN05_FENCE_AFTER() \
    asm volatile("tcgen05.fence::after_thread_sync;" ::: "memory")
#define TCGEN05_WAIT_LD() \
    asm volatile("tcgen05.wait::ld.sync.aligned;" ::: "memory")
#define MBARRIER_INIT(mbar_smem_addr, count) \
    asm volatile("mbarrier.init.shared.b64 [%0], %1;" \
                 :: "r"((uint32_t)(mbar_smem_addr)), "r"((uint32_t)(count)) : "memory")
#define MBARRIER_EXPECT_TX(mbar_smem_addr, tx_bytes) \
    asm volatile("mbarrier.arrive.expect_tx.shared.b64 _, [%0], %1;" \
                 :: "r"((uint32_t)(mbar_smem_addr)), "r"((uint32_t)(tx_bytes)) : "memory")
#define FENCE_PROXY_ASYNC_SHARED_CTA() \
    asm volatile("fence.proxy.async.shared::cta;" ::: "memory")

#define MBARRIER_WAIT_PARITY(mbar_smem_addr, phase_parity) do { \
    uint32_t _mbar = (uint32_t)(mbar_smem_addr); \
    uint32_t _parity = (uint32_t)(phase_parity); \
    uint32_t _done; \
    asm volatile( \
        "{\n\t.reg .pred p;\n\t" \
        "mbarrier.try_wait.parity.acquire.cta.shared::cta.b64 p, [%1], %2;\n\t" \
        "selp.b32 %0, 1, 0, p;\n\t}" \
        : "=r"(_done) : "r"(_mbar), "r"(_parity) : "memory"); \
    if (!_done) { \
        asm volatile( \
            "{\n\t.reg .pred P1;\n\t" \
            "WAIT_LOOP_%=:\n\t" \
            "mbarrier.try_wait.parity.acquire.cta.shared::cta.b64 P1, [%0], %1, 0x989680;\n\t" \
            "@P1 bra.uni WAIT_DONE_%=;\n\t" \
            "bra.uni WAIT_LOOP_%=;\n\t" \
            "WAIT_DONE_%=:\n\t}" \
            :: "r"(_mbar), "r"(_parity) : "memory"); \
    } \
} while(0)

#define TCGEN05_LD_32X32B_X32(r, tmem_addr) \
    asm volatile( \
        "tcgen05.ld.sync.aligned.32x32b.x32.b32 " \
        "{%0, %1, %2, %3, %4, %5, %6, %7, " \
        " %8, %9, %10, %11, %12, %13, %14, %15, " \
        " %16, %17, %18, %19, %20, %21, %22, %23, " \
        " %24, %25, %26, %27, %28, %29, %30, %31}, [%32];" \
        : "=r"((r)[0]),  "=r"((r)[1]),  "=r"((r)[2]),  "=r"((r)[3]), \
          "=r"((r)[4]),  "=r"((r)[5]),  "=r"((r)[6]),  "=r"((r)[7]), \
          "=r"((r)[8]),  "=r"((r)[9]),  "=r"((r)[10]), "=r"((r)[11]), \
          "=r"((r)[12]), "=r"((r)[13]), "=r"((r)[14]), "=r"((r)[15]), \
          "=r"((r)[16]), "=r"((r)[17]), "=r"((r)[18]), "=r"((r)[19]), \
          "=r"((r)[20]), "=r"((r)[21]), "=r"((r)[22]), "=r"((r)[23]), \
          "=r"((r)[24]), "=r"((r)[25]), "=r"((r)[26]), "=r"((r)[27]), \
          "=r"((r)[28]), "=r"((r)[29]), "=r"((r)[30]), "=r"((r)[31]) \
        : "r"(tmem_addr))

#define TCGEN05_MMA_TF32_SS(d_tmem, a_desc, b_desc, idesc, enable_d) do { \
    uint32_t _en = (enable_d) ? 1u : 0u; \
    uint32_t _zero = 0u; \
    asm volatile( \
        "{\n\t.reg .pred p;\n\t" \
        "setp.ne.u32 p, %5, 0;\n\t" \
        "tcgen05.mma.cta_group::1.kind::tf32 [%0], %1, %2, %3, {%4, %4, %4, %4}, p;\n\t" \
        "}" \
        :: "r"(d_tmem), "l"(a_desc), "l"(b_desc), "r"(idesc), "r"(_zero), "r"(_en) \
        : "memory"); \
} while(0)

static constexpr uint64_t SMEM_DESC_BASE_SW128 =
    (uint64_t(2)  << 61) | (uint64_t(1) << 46) | (uint64_t(64) << 32) | (uint64_t(1) << 16);
#define MAKE_SMEM_DESC(base_addr) \
    (SMEM_DESC_BASE_SW128 | ((uint64_t)((base_addr) >> 4) & 0x3FFF))

#define CP_ASYNC_BULK(dst_smem, src_gmem, bytes, mbar) \
    asm volatile("cp.async.bulk.shared::cta.global.mbarrier::complete_tx::bytes " \
                 "[%0], [%1], %2, [%3];" \
                 :: "r"((uint32_t)(dst_smem)), "l"(src_gmem), \
                    "r"((uint32_t)(bytes)), "r"((uint32_t)(mbar)) : "memory")

// IDESC for tf32, F32 accum, M=128, N=256
static constexpr uint32_t IDESC_128x256 =
    (1u << 4) | (2u << 7) | (2u << 10) | ((256 / 8) << 17) | ((128 / 16) << 24);
#endif  // HAS_TCGEN05

// ---------------------------------------------------------------------------
// Merged projection GEMM (3xTF32): one launch, grid (3, kM/128).
// blockIdx.x selects {Wq->Qb blocked}, {Wk->Kb blocked}, {Wv->V row-major}.
// ---------------------------------------------------------------------------
static constexpr int PROJ_SMEM = 4096 + 98304;

__global__ __launch_bounds__(256)
void proj_gemm(const float* __restrict__ A,
               const float* __restrict__ W0, const float* __restrict__ W1,
               const float* __restrict__ W2,
               const float* __restrict__ b0, const float* __restrict__ b1,
               const float* __restrict__ b2,
               float* __restrict__ C0, float* __restrict__ C1,
               float* __restrict__ C2)
{
    extern __shared__ __align__(1024) char smem[];
    const int tid = threadIdx.x;
    const int bx = blockIdx.x;
    const int bm = blockIdx.y * 128;
    constexpr int N = 256, K = 256;

    const float* Bm  = (bx == 0) ? W0 : (bx == 1) ? W1 : W2;
    const float* bias = (bx == 0) ? b0 : (bx == 1) ? b1 : b2;
    float* C = (bx == 0) ? C0 : (bx == 1) ? C1 : C2;
    const int mode = (bx == 2) ? 1 : 0;

#if HAS_TCGEN05
    const uint32_t sb = smem_to_u32_gen(smem);
    const uint32_t mbar = sb;
    float* s_bias = (float*)(smem + 64);
    const int wid = tid >> 5;

    if (wid == 0) { TCGEN05_ALLOC(sb + 8, 256); TCGEN05_RELINQUISH(); }
    if (tid == 0) MBARRIER_INIT(mbar, 1);
    s_bias[tid] = bias[tid];
    __syncthreads();
    const uint32_t tmem = *(volatile uint32_t*)(smem + 8);

    const uint32_t tAh = sb + 4096;
    const uint32_t tAl = tAh + 16384;
    const uint32_t tBh = tAl + 16384;
    const uint32_t tBl = tBh + 32768;
    const uint64_t dAh = MAKE_SMEM_DESC(tAh);
    const uint64_t dAl = MAKE_SMEM_DESC(tAl);
    const uint64_t dBh = MAKE_SMEM_DESC(tBh);
    const uint64_t dBl = MAKE_SMEM_DESC(tBl);

    for (int c = 0; c < K / 32; c++) {
        const int k0 = c * 32;
        __syncthreads();
#pragma unroll
        for (int t = 0; t < 4; t++) {
            int idx = tid + t * 256;
            int row = idx >> 3, c4 = idx & 7;
            uint32_t sw = SMEM_SWIZZLE_128B((uint32_t)(row * 128 + c4 * 16));
            float4 v = *(const float4*)(A + (size_t)(bm + row) * K + k0 + c4 * 4);
            float4 h, l;
            h.x = to_tf32(v.x); l.x = to_tf32(v.x - h.x);
            h.y = to_tf32(v.y); l.y = to_tf32(v.y - h.y);
            h.z = to_tf32(v.z); l.z = to_tf32(v.z - h.z);
            h.w = to_tf32(v.w); l.w = to_tf32(v.w - h.w);
            *(float4*)(smem + (tAh - sb) + sw) = h;
            *(float4*)(smem + (tAl - sb) + sw) = l;
        }
#pragma unroll
        for (int t = 0; t < 8; t++) {
            int idx = tid + t * 256;
            int row = idx >> 3, c4 = idx & 7;
            uint32_t sw = SMEM_SWIZZLE_128B((uint32_t)(row * 128 + c4 * 16));
            float4 v = *(const float4*)(Bm + (size_t)row * K + k0 + c4 * 4);
            float4 h, l;
            h.x = to_tf32(v.x); l.x = to_tf32(v.x - h.x);
            h.y = to_tf32(v.y); l.y = to_tf32(v.y - h.y);
            h.z = to_tf32(v.z); l.z = to_tf32(v.z - h.z);
            h.w = to_tf32(v.w); l.w = to_tf32(v.w - h.w);
            *(float4*)(smem + (tBh - sb) + sw) = h;
            *(float4*)(smem + (tBl - sb) + sw) = l;
        }
        FENCE_PROXY_ASYNC_SHARED_CTA();
        __syncthreads();

        if (wid == 0 && elect_one_pred()) {
#pragma unroll
            for (int k = 0; k < 4; k++)
                TCGEN05_MMA_TF32_SS(tmem, dAh + k * 2, dBh + k * 2, IDESC_128x256,
                                    (c > 0) || (k > 0));
#pragma unroll
            for (int k = 0; k < 4; k++)
                TCGEN05_MMA_TF32_SS(tmem, dAh + k * 2, dBl + k * 2, IDESC_128x256, true);
#pragma unroll
            for (int k = 0; k < 4; k++)
                TCGEN05_MMA_TF32_SS(tmem, dAl + k * 2, dBh + k * 2, IDESC_128x256, true);
            TCGEN05_COMMIT(mbar);
        }
        MBARRIER_WAIT_PARITY(mbar, c & 1);
    }

    TCGEN05_FENCE_AFTER();

    if (wid < 4) {
        const int lane = tid & 31;
        const int mloc = wid * 32 + lane;
        const int m = bm + mloc;
#pragma unroll
        for (int g = 0; g < 8; g++) {
            uint32_t r[32];
            TCGEN05_LD_32X32B_X32(r, tmem + g * 32);
            TCGEN05_WAIT_LD();
            const int col0 = g * 32;
            if (mode == 0) {
#pragma unroll
                for (int j = 0; j < 32; j++)
                    r[j] = __float_as_uint(
                        to_tf32(__uint_as_float(r[j]) + s_bias[col0 + j]));
                float* blk = C + (((size_t)(m >> 7) * 8 + g) << 12);
#pragma unroll
                for (int j = 0; j < 8; j++) {
                    uint32_t sw = SMEM_SWIZZLE_128B((uint32_t)(mloc * 128 + j * 16));
                    *(float4*)((char*)blk + sw) = *(float4*)&r[j * 4];
                }
            } else {
#pragma unroll
                for (int j = 0; j < 32; j++)
                    r[j] = __float_as_uint(__uint_as_float(r[j]) + s_bias[col0 + j]);
                float* crow = C + (size_t)m * N;
#pragma unroll
                for (int j = 0; j < 8; j++)
                    *(float4*)&crow[col0 + j * 4] = *(float4*)&r[j * 4];
            }
        }
    }
    __syncthreads();
    if (wid == 0) TCGEN05_DEALLOC(tmem, 256);

#else
    // SIMT fallback
    constexpr int BK = 16, TM = 8, TN = 8;
    float* As = (float*)smem;
    float* Bs = As + BK * 128;
    const int tx = tid & 15, ty = tid >> 4;

    for (int nh = 0; nh < 2; nh++) {
        const int bn2 = nh * 128;
        float acc[TM][TN];
#pragma unroll
        for (int i = 0; i < TM; i++)
#pragma unroll
            for (int j = 0; j < TN; j++) acc[i][j] = 0.0f;

        for (int k0 = 0; k0 < K; k0 += BK) {
            __syncthreads();
#pragma unroll
            for (int i = 0; i < 2; i++) {
                int li = tid + i * 256;
                int row = li >> 2, kc = (li & 3) << 2;
                float4 va = *(const float4*)(A + (size_t)(bm + row) * K + k0 + kc);
                As[(kc + 0) * 128 + row] = va.x; As[(kc + 1) * 128 + row] = va.y;
                As[(kc + 2) * 128 + row] = va.z; As[(kc + 3) * 128 + row] = va.w;
                float4 vb = *(const float4*)(Bm + (size_t)(bn2 + row) * K + k0 + kc);
                Bs[(kc + 0) * 128 + row] = vb.x; Bs[(kc + 1) * 128 + row] = vb.y;
                Bs[(kc + 2) * 128 + row] = vb.z; Bs[(kc + 3) * 128 + row] = vb.w;
            }
            __syncthreads();
#pragma unroll
            for (int kk = 0; kk < BK; kk++) {
                float a[TM], bb[TN];
                *(float4*)&a[0]  = *(const float4*)&As[kk * 128 + ty * TM];
                *(float4*)&a[4]  = *(const float4*)&As[kk * 128 + ty * TM + 4];
                *(float4*)&bb[0] = *(const float4*)&Bs[kk * 128 + tx * TN];
                *(float4*)&bb[4] = *(const float4*)&Bs[kk * 128 + tx * TN + 4];
#pragma unroll
                for (int i = 0; i < TM; i++)
#pragma unroll
                    for (int j = 0; j < TN; j++)
                        acc[i][j] = fmaf(a[i], bb[j], acc[i][j]);
            }
        }
        const int row0 = bm + ty * TM, col0 = bn2 + tx * TN;
#pragma unroll
        for (int i = 0; i < TM; i++)
#pragma unroll
            for (int j = 0; j < TN; j++) {
                float v = acc[i][j] + bias[col0 + j];
                int m = row0 + i, n = col0 + j;
                if (mode == 0)
                    C[qk_blk_off(m >> 7, n >> 5, m & 127, n & 31)] = to_tf32(v);
                else
                    C[(size_t)m * N + n] = v;
            }
        __syncthreads();
    }
#endif
}

// ---------------------------------------------------------------------------
// Scores GEMM: E[b,m,n] = exp((q.k)*scale) * maskfac(n), plus per-CTA row-sum
// partials rpart[nx][b][m]. BM=128, BN=256, cp.async.bulk 2-stage pipeline.
// ---------------------------------------------------------------------------
static constexpr int SC_STAGE = 49152;
static constexpr int SC_SMEM = 4096 + 2 * SC_STAGE;

__global__ __launch_bounds__(256)
void score_gemm(const float* __restrict__ Qb, const float* __restrict__ Kb,
                const int* __restrict__ mask, float* __restrict__ P,
                float* __restrict__ rpart, float scale)
{
    extern __shared__ __align__(1024) char smem[];
    const int tid = threadIdx.x;
    const int bz = blockIdx.z;
    float* C = P + (size_t)bz * kS * kS;
    const int* mk = mask + (size_t)bz * kS;

    const int my = blockIdx.y;
    const int nx = blockIdx.x;
    const int bm = my * 128;
    const int bn = nx * 256;

#if HAS_TCGEN05
    const uint32_t sb = smem_to_u32_gen(smem);
    const uint32_t m_full0 = sb + 0,  m_full1 = sb + 8;
    const uint32_t m_emp0  = sb + 16, m_emp1  = sb + 24;
    const uint32_t m_done  = sb + 32;
    float* s_mf = (float*)(smem + 64);
    const int wid = tid >> 5;

    if (wid == 0) { TCGEN05_ALLOC(sb + 40, 256); TCGEN05_RELINQUISH(); }
    if (tid == 0) {
        MBARRIER_INIT(m_full0, 1);
        MBARRIER_INIT(m_full1, 1);
        MBARRIER_INIT(m_emp0, 1);
        MBARRIER_INIT(m_emp1, 1);
        MBARRIER_INIT(m_done, 1);
    }
    s_mf[tid] = (mk[bn + tid] != 0) ? 1.0f : 0.0f;
    __syncthreads();
    const uint32_t tmem = *(volatile uint32_t*)(smem + 40);

    uint64_t dA[2], dB[2];
#pragma unroll
    for (int s = 0; s < 2; s++) {
        uint32_t base = sb + 4096 + s * SC_STAGE;
        dA[s] = MAKE_SMEM_DESC(base);
        dB[s] = MAKE_SMEM_DESC(base + 16384);
    }

    const int amt = bz * 16 + my;
    const int bmt0 = bz * 16 + nx * 2;

    if (wid == 1) {
        if (elect_one_pred()) {
            for (int c = 0; c < 8; c++) {
                const int s = c & 1;
                const int i = c >> 1;
                const uint32_t m_full = s ? m_full1 : m_full0;
                const uint32_t m_emp  = s ? m_emp1  : m_emp0;
                const uint32_t st = sb + 4096 + s * SC_STAGE;
                MBARRIER_WAIT_PARITY(m_emp, 1 ^ (i & 1));
                MBARRIER_EXPECT_TX(m_full, SC_STAGE);
                CP_ASYNC_BULK(st,
                              Qb + (((size_t)amt * 8 + c) << 12), 16384, m_full);
                CP_ASYNC_BULK(st + 16384,
                              Kb + (((size_t)bmt0 * 8 + c) << 12), 16384, m_full);
                CP_ASYNC_BULK(st + 32768,
                              Kb + (((size_t)(bmt0 + 1) * 8 + c) << 12), 16384, m_full);
            }
        }
    } else if (wid == 0) {
        if (elect_one_pred()) {
            for (int c = 0; c < 8; c++) {
                const int s = c & 1;
                const int i = c >> 1;
                const uint32_t m_full = s ? m_full1 : m_full0;
                const uint32_t m_emp  = s ? m_emp1  : m_emp0;
                MBARRIER_WAIT_PARITY(m_full, i & 1);
#pragma unroll
                for (int k = 0; k < 4; k++)
                    TCGEN05_MMA_TF32_SS(tmem, dA[s] + k * 2, dB[s] + k * 2,
                                        IDESC_128x256, (c > 0) || (k > 0));
                TCGEN05_COMMIT(m_emp);
            }
            TCGEN05_COMMIT(m_done);
        }
    }

    MBARRIER_WAIT_PARITY(m_done, 0);
    TCGEN05_FENCE_AFTER();

    if (wid < 4) {
        const int lane = tid & 31;
        const int m = bm + wid * 32 + lane;
        float* crow = C + (size_t)m * kS + bn;
        float rs = 0.0f;
#pragma unroll
        for (int g = 0; g < 8; g++) {
            uint32_t r[32];
            TCGEN05_LD_32X32B_X32(r, tmem + g * 32);
            TCGEN05_WAIT_LD();
            const int col0 = g * 32;
#pragma unroll
            for (int j = 0; j < 32; j++) {
                float e = __expf(__uint_as_float(r[j]) * scale) * s_mf[col0 + j];
                rs += e;
                r[j] = __float_as_uint(e);
            }
#pragma unroll
            for (int j = 0; j < 8; j++)
                *(float4*)&crow[col0 + j * 4] = *(float4*)&r[j * 4];
        }
        rpart[((size_t)nx * kB + bz) * kS + m] = rs;
    }
    __syncthreads();
    if (wid == 0) TCGEN05_DEALLOC(tmem, 256);

#else
    // SIMT fallback — reads blocked Q/K layout, writes E + rpart.
    constexpr int BK = 16, TM = 8, TN = 8;
    float* As = (float*)smem;
    float* Bs = As + BK * 128;
    const int tx = tid & 15, ty = tid >> 4;
    const int amt = bz * 16 + my;
    const int bmt0 = bz * 16 + nx * 2;

    float rs[TM];
#pragma unroll
    for (int i = 0; i < TM; i++) rs[i] = 0.0f;

    for (int nh = 0; nh < 2; nh++) {
        const int bmtl = bmt0 + nh;
        float acc[TM][TN];
#pragma unroll
        for (int i = 0; i < TM; i++)
#pragma unroll
            for (int j = 0; j < TN; j++) acc[i][j] = 0.0f;

        for (int k0 = 0; k0 < kD; k0 += BK) {
            __syncthreads();
            for (int li = tid; li < 128 * BK; li += 256) {
                int row = li / BK, kc = li % BK;
                As[kc * 128 + row] =
                    Qb[qk_blk_off(amt, (k0 + kc) >> 5, row, (k0 + kc) & 31)];
                Bs[kc * 128 + row] =
                    Kb[qk_blk_off(bmtl, (k0 + kc) >> 5, row, (k0 + kc) & 31)];
            }
            __syncthreads();
#pragma unroll
            for (int kk = 0; kk < BK; kk++) {
                float a[TM], bb[TN];
                *(float4*)&a[0]  = *(const float4*)&As[kk * 128 + ty * TM];
                *(float4*)&a[4]  = *(const float4*)&As[kk * 128 + ty * TM + 4];
                *(float4*)&bb[0] = *(const float4*)&Bs[kk * 128 + tx * TN];
                *(float4*)&bb[4] = *(const float4*)&Bs[kk * 128 + tx * TN + 4];
#pragma unroll
                for (int i = 0; i < TM; i++)
#pragma unroll
                    for (int j = 0; j < TN; j++)
                        acc[i][j] = fmaf(a[i], bb[j], acc[i][j]);
            }
        }
        const int row0 = bm + ty * TM, col0 = nh * 128 + bn + tx * TN;
#pragma unroll
        for (int i = 0; i < TM; i++)
#pragma unroll
            for (int j = 0; j < TN; j++) {
                float e = __expf(acc[i][j] * scale)
                          * ((mk[col0 + j] != 0) ? 1.0f : 0.0f);
                C[(size_t)(row0 + i) * kS + col0 + j] = e;
                rs[i] += e;
            }
        __syncthreads();
    }
    // reduce row sums across the 16 tx lanes (bits 0-3 of lane id)
#pragma unroll
    for (int i = 0; i < TM; i++) {
        float v = rs[i];
#pragma unroll
        for (int o = 8; o; o >>= 1) v += __shfl_xor_sync(0xffffffffu, v, o);
        if (tx == 0)
            rpart[((size_t)nx * kB + bz) * kS + bm + ty * TM + i] = v;
    }
#endif
}

// ---------------------------------------------------------------------------
// invr[b,q] = 1 / sum_nx rpart[nx][b][q]
// ---------------------------------------------------------------------------
__global__ __launch_bounds__(256)
void rowsum_reduce_kernel(const float* __restrict__ rpart, float* __restrict__ invr)
{
    const int i = blockIdx.x * 256 + threadIdx.x;
    float s = 0.0f;
#pragma unroll
    for (int c = 0; c < NXT; c++) s += rpart[(size_t)c * (kB * kS) + i];
    invr[i] = 1.0f / s;
}

// ---------------------------------------------------------------------------
// Column-sum stream: w[b,k] += E[b,q,k] * invr[b,q]. No barriers.
// Block = 256 threads handles 32 rows; thread owns cols [tid*8, tid*8+8).
// ---------------------------------------------------------------------------
__global__ __launch_bounds__(256)
void colsum_stream_kernel(const float* __restrict__ P,
                          const float* __restrict__ invr,
                          float* __restrict__ wpart)
{
    const int ch = blockIdx.x;
    const int b  = blockIdx.y;
    const int tid = threadIdx.x;
    const float* base = P + ((size_t)b * kS + (size_t)ch * 32) * kS;
    const float* iv = invr + (size_t)b * kS + (size_t)ch * 32;

    float wacc[8];
#pragma unroll
    for (int i = 0; i < 8; i++) wacc[i] = 0.0f;

    for (int r = 0; r < 32; r++) {
        const float s = iv[r];
        const float* p = base + (size_t)r * kS + tid * 8;
        float x[8];
        *(float4*)&x[0] = *(const float4*)&p[0];
        *(float4*)&x[4] = *(const float4*)&p[4];
#pragma unroll
        for (int i = 0; i < 8; i++) wacc[i] = fmaf(x[i], s, wacc[i]);
    }

    float* o = wpart + (size_t)ch * (kB * kS) + (size_t)b * kS + tid * 8;
    *(float4*)&o[0] = make_float4(wacc[0], wacc[1], wacc[2], wacc[3]);
    *(float4*)&o[4] = make_float4(wacc[4], wacc[5], wacc[6], wacc[7]);
}

__global__ __launch_bounds__(256)
void colsum_reduce_kernel(const float* __restrict__ wpart, float* __restrict__ w)
{
    const int i = blockIdx.x * 256 + threadIdx.x;
    float s = 0.0f;
#pragma unroll
    for (int c = 0; c < QCH; c++) s += wpart[(size_t)c * (kB * kS) + i];
    w[i] = s;
}

__global__ __launch_bounds__(256)
void out_part_kernel(const float* __restrict__ w, const float* __restrict__ V,
                     float* __restrict__ opart)
{
    const int chunk = blockIdx.x;
    const int b     = blockIdx.y;
    const int d     = threadIdx.x;
    const float* vb = V + ((size_t)b * kS + (size_t)chunk * 64) * kD;
    const float* wb = w + b * kS + chunk * 64;
    float s = 0.0f;
#pragma unroll
    for (int k = 0; k < 64; k++) s = fmaf(wb[k], vb[(size_t)k * kD + d], s);
    opart[(size_t)(chunk * kB + b) * kD + d] = s;
}

__global__ __launch_bounds__(256)
void out_reduce_kernel(const float* __restrict__ opart, float* __restrict__ out)
{
    const int i = blockIdx.x * 256 + threadIdx.x;
    float s = 0.0f;
#pragma unroll
    for (int c = 0; c < N_KCHUNK; c++) s += opart[(size_t)c * (kB * kD) + i];
    out[i] = s * (1.0f / (float)kS);
}

// ---------------------------------------------------------------------------
// Launch
// ---------------------------------------------------------------------------
extern "C" void kernel_launch(void* const* d_in, const int* in_sizes, int n_in,
                              void* d_out, int out_size)
{
    const float* nodes = (const float*)d_in[0];
    const int*   mask  = (const int*)  d_in[1];
    const float* Wq    = (const float*)d_in[2];
    const float* bq    = (const float*)d_in[3];
    const float* Wk    = (const float*)d_in[4];
    const float* bk    = (const float*)d_in[5];
    const float* Wv    = (const float*)d_in[6];
    const float* bv    = (const float*)d_in[7];
    float* out = (float*)d_out;

    float *Qb, *Kb, *V, *P, *rpart, *invr, *w, *wpart, *opart;
    cudaGetSymbolAddress((void**)&Qb,    g_Qb);
    cudaGetSymbolAddress((void**)&Kb,    g_Kb);
    cudaGetSymbolAddress((void**)&V,     g_V);
    cudaGetSymbolAddress((void**)&P,     g_P);
    cudaGetSymbolAddress((void**)&rpart, g_rpart);
    cudaGetSymbolAddress((void**)&invr,  g_invr);
    cudaGetSymbolAddress((void**)&w,     g_w);
    cudaGetSymbolAddress((void**)&wpart, g_wpart);
    cudaGetSymbolAddress((void**)&opart, g_opart);

    cudaFuncSetAttribute(proj_gemm,
                         cudaFuncAttributeMaxDynamicSharedMemorySize, PROJ_SMEM);
    cudaFuncSetAttribute(score_gemm,
                         cudaFuncAttributeMaxDynamicSharedMemorySize, SC_SMEM);

    dim3 blk(256);

    // 1. All three projections in one launch (3xTF32, 384 CTAs).
    dim3 gproj(3, kM / 128, 1);
    proj_gemm<<<gproj, blk, PROJ_SMEM>>>(nodes, Wq, Wk, Wv, bq, bk, bv,
                                         Qb, Kb, V);

    // 2. Scores -> E = exp(score/16) with masked cols = 0, + rowsum partials
    dim3 gsc(kS / 256, kS / 128, kB);
    score_gemm<<<gsc, blk, SC_SMEM>>>(Qb, Kb, mask, P, rpart, 0.0625f);

    // 3. rowsum -> invr, stream colsum, reduce, output contraction
    rowsum_reduce_kernel<<<(kB * kS) / 256, blk>>>(rpart, invr);
    colsum_stream_kernel<<<dim3(QCH, kB), blk>>>(P, invr, wpart);
    colsum_reduce_kernel<<<(kB * kS) / 256, blk>>>(wpart, w);
    out_part_kernel<<<dim3(N_KCHUNK, kB), blk>>>(w, V, opart);
    out_reduce_kernel<<<(kB * kD) / 256, blk>>>(opart, out);
}

// round 9
// speedup vs baseline: 1.6813x; 1.2471x over previous
#include <cuda_runtime.h>
#include <cuda_bf16.h>
#include <cstdint>
#include <math.h>

// ---------------------------------------------------------------------------
// Problem constants
// ---------------------------------------------------------------------------
static constexpr int kB = 8;
static constexpr int kS = 2048;
static constexpr int kD = 256;
static constexpr int kM = kB * kS;
static constexpr int QCH = 64;       // colsum: 32 rows per chunk
static constexpr int N_KCHUNK = 32;  // output split over keys
static constexpr int NXT = kS / 256; // 8 n-tiles per batch row

// Scratch (static device memory)
// Q, K stored BLOCKED: block = [128 rows x 32 cols] = 16KB, SW128-swizzled.
__device__ float g_Qb[kB * kS * kD];
__device__ float g_Kb[kB * kS * kD];
__device__ float g_V[kB * kS * kD];                    // row-major fp32
__device__ __nv_bfloat16 g_E[(size_t)kB * kS * kS];    // exp scores (bf16)
__device__ float g_rpart[NXT * kB * kS];               // row-sum partials
__device__ float g_invr[kB * kS];                      // 1 / rowsum
__device__ float g_w[kB * kS];
__device__ float g_wpart[QCH * kB * kS];
__device__ float g_opart[N_KCHUNK * kB * kD];

#if defined(__CUDA_ARCH__) && defined(__CUDA_ARCH_FEAT_SM103_ALL)
#define HAS_TCGEN05 1
#else
#define HAS_TCGEN05 0
#endif

#define SMEM_SWIZZLE_128B(byte_offset) \
    ((byte_offset) ^ (((byte_offset) >> 3) & 0x70))

__device__ __forceinline__ uint32_t smem_to_u32_gen(const void* p) {
    uint32_t a;
    asm("{ .reg .u64 t; cvta.to.shared.u64 t, %1; cvt.u32.u64 %0, t; }"
        : "=r"(a) : "l"(p));
    return a;
}

__device__ __forceinline__ float to_tf32(float x) {
    float y;
    asm("cvt.rna.tf32.f32 %0, %1;" : "=f"(y) : "f"(x));
    return y;
}

// pack two floats into bf16x2 (lo in low half)
__device__ __forceinline__ uint32_t pack_bf16x2(float lo, float hi) {
    uint32_t r;
    asm("cvt.rn.bf16x2.f32 %0, %1, %2;" : "=r"(r) : "f"(hi), "f"(lo));
    return r;
}

// float-index offset of element (row m in [0,128), col c in [0,32)) inside a
// 16KB swizzled block.
__device__ __forceinline__ size_t qk_blk_off(int gmtile, int kchunk, int r, int c) {
    uint32_t byte = (uint32_t)(r * 128 + (c >> 2) * 16);
    uint32_t sw = SMEM_SWIZZLE_128B(byte) + (uint32_t)(c & 3) * 4;
    return ((size_t)(gmtile * 8 + kchunk) << 12) + (sw >> 2);
}

#if HAS_TCGEN05
__device__ __forceinline__ uint32_t elect_one_pred() {
    uint32_t pred;
    asm volatile(
        "{\n\t.reg .pred p;\n\t"
        "elect.sync _|p, 0xFFFFFFFF;\n\t"
        "selp.b32 %0, 1, 0, p;\n\t}"
        : "=r"(pred));
    return pred;
}

#define TCGEN05_ALLOC(smem_result_addr, nCols) \
    asm volatile("tcgen05.alloc.cta_group::1.sync.aligned.shared::cta.b32 [%0], %1;" \
                 :: "r"((uint32_t)(smem_result_addr)), "r"((uint32_t)(nCols)) : "memory")
#define TCGEN05_DEALLOC(tmem_addr, nCols) \
    asm volatile("tcgen05.dealloc.cta_group::1.sync.aligned.b32 %0, %1;" \
                 :: "r"(tmem_addr), "r"((uint32_t)(nCols)))
#define TCGEN05_RELINQUISH() \
    asm volatile("tcgen05.relinquish_alloc_permit.cta_group::1.sync.aligned;")
#define TCGEN05_COMMIT(mbar_smem_addr) \
    asm volatile("tcgen05.commit.cta_group::1.mbarrier::arrive::one.shared::cluster.b64 [%0];" \
                 :: "r"((uint32_t)(mbar_smem_addr)) : "memory")
#define TCGEN05_FENCE_AFTER() \
    asm volatile("tcgen05.fence::after_thread_sync;" ::: "memory")
#define TCGEN05_WAIT_LD() \
    asm volatile("tcgen05.wait::ld.sync.aligned;" ::: "memory")
#define MBARRIER_INIT(mbar_smem_addr, count) \
    asm volatile("mbarrier.init.shared.b64 [%0], %1;" \
                 :: "r"((uint32_t)(mbar_smem_addr)), "r"((uint32_t)(count)) : "memory")
#define MBARRIER_EXPECT_TX(mbar_smem_addr, tx_bytes) \
    asm volatile("mbarrier.arrive.expect_tx.shared.b64 _, [%0], %1;" \
                 :: "r"((uint32_t)(mbar_smem_addr)), "r"((uint32_t)(tx_bytes)) : "memory")
#define FENCE_PROXY_ASYNC_SHARED_CTA() \
    asm volatile("fence.proxy.async.shared::cta;" ::: "memory")

#define MBARRIER_WAIT_PARITY(mbar_smem_addr, phase_parity) do { \
    uint32_t _mbar = (uint32_t)(mbar_smem_addr); \
    uint32_t _parity = (uint32_t)(phase_parity); \
    uint32_t _done; \
    asm volatile( \
        "{\n\t.reg .pred p;\n\t" \
        "mbarrier.try_wait.parity.acquire.cta.shared::cta.b64 p, [%1], %2;\n\t" \
        "selp.b32 %0, 1, 0, p;\n\t}" \
        : "=r"(_done) : "r"(_mbar), "r"(_parity) : "memory"); \
    if (!_done) { \
        asm volatile( \
            "{\n\t.reg .pred P1;\n\t" \
            "WAIT_LOOP_%=:\n\t" \
            "mbarrier.try_wait.parity.acquire.cta.shared::cta.b64 P1, [%0], %1, 0x989680;\n\t" \
            "@P1 bra.uni WAIT_DONE_%=;\n\t" \
            "bra.uni WAIT_LOOP_%=;\n\t" \
            "WAIT_DONE_%=:\n\t}" \
            :: "r"(_mbar), "r"(_parity) : "memory"); \
    } \
} while(0)

#define TCGEN05_LD_32X32B_X32(r, tmem_addr) \
    asm volatile( \
        "tcgen05.ld.sync.aligned.32x32b.x32.b32 " \
        "{%0, %1, %2, %3, %4, %5, %6, %7, " \
        " %8, %9, %10, %11, %12, %13, %14, %15, " \
        " %16, %17, %18, %19, %20, %21, %22, %23, " \
        " %24, %25, %26, %27, %28, %29, %30, %31}, [%32];" \
        : "=r"((r)[0]),  "=r"((r)[1]),  "=r"((r)[2]),  "=r"((r)[3]), \
          "=r"((r)[4]),  "=r"((r)[5]),  "=r"((r)[6]),  "=r"((r)[7]), \
          "=r"((r)[8]),  "=r"((r)[9]),  "=r"((r)[10]), "=r"((r)[11]), \
          "=r"((r)[12]), "=r"((r)[13]), "=r"((r)[14]), "=r"((r)[15]), \
          "=r"((r)[16]), "=r"((r)[17]), "=r"((r)[18]), "=r"((r)[19]), \
          "=r"((r)[20]), "=r"((r)[21]), "=r"((r)[22]), "=r"((r)[23]), \
          "=r"((r)[24]), "=r"((r)[25]), "=r"((r)[26]), "=r"((r)[27]), \
          "=r"((r)[28]), "=r"((r)[29]), "=r"((r)[30]), "=r"((r)[31]) \
        : "r"(tmem_addr))

#define TCGEN05_MMA_TF32_SS(d_tmem, a_desc, b_desc, idesc, enable_d) do { \
    uint32_t _en = (enable_d) ? 1u : 0u; \
    uint32_t _zero = 0u; \
    asm volatile( \
        "{\n\t.reg .pred p;\n\t" \
        "setp.ne.u32 p, %5, 0;\n\t" \
        "tcgen05.mma.cta_group::1.kind::tf32 [%0], %1, %2, %3, {%4, %4, %4, %4}, p;\n\t" \
        "}" \
        :: "r"(d_tmem), "l"(a_desc), "l"(b_desc), "r"(idesc), "r"(_zero), "r"(_en) \
        : "memory"); \
} while(0)

static constexpr uint64_t SMEM_DESC_BASE_SW128 =
    (uint64_t(2)  << 61) | (uint64_t(1) << 46) | (uint64_t(64) << 32) | (uint64_t(1) << 16);
#define MAKE_SMEM_DESC(base_addr) \
    (SMEM_DESC_BASE_SW128 | ((uint64_t)((base_addr) >> 4) & 0x3FFF))

#define CP_ASYNC_BULK(dst_smem, src_gmem, bytes, mbar) \
    asm volatile("cp.async.bulk.shared::cta.global.mbarrier::complete_tx::bytes " \
                 "[%0], [%1], %2, [%3];" \
                 :: "r"((uint32_t)(dst_smem)), "l"(src_gmem), \
                    "r"((uint32_t)(bytes)), "r"((uint32_t)(mbar)) : "memory")

// IDESC for tf32, F32 accum, M=128, N=256
static constexpr uint32_t IDESC_128x256 =
    (1u << 4) | (2u << 7) | (2u << 10) | ((256 / 8) << 17) | ((128 / 16) << 24);
#endif  // HAS_TCGEN05

// ---------------------------------------------------------------------------
// Merged projection GEMM (3xTF32): one launch, grid (3, kM/128).
// ---------------------------------------------------------------------------
static constexpr int PROJ_SMEM = 4096 + 98304;

__global__ __launch_bounds__(256)
void proj_gemm(const float* __restrict__ A,
               const float* __restrict__ W0, const float* __restrict__ W1,
               const float* __restrict__ W2,
               const float* __restrict__ b0, const float* __restrict__ b1,
               const float* __restrict__ b2,
               float* __restrict__ C0, float* __restrict__ C1,
               float* __restrict__ C2)
{
    extern __shared__ __align__(1024) char smem[];
    const int tid = threadIdx.x;
    const int bx = blockIdx.x;
    const int bm = blockIdx.y * 128;
    constexpr int N = 256, K = 256;

    const float* Bm  = (bx == 0) ? W0 : (bx == 1) ? W1 : W2;
    const float* bias = (bx == 0) ? b0 : (bx == 1) ? b1 : b2;
    float* C = (bx == 0) ? C0 : (bx == 1) ? C1 : C2;
    const int mode = (bx == 2) ? 1 : 0;

#if HAS_TCGEN05
    const uint32_t sb = smem_to_u32_gen(smem);
    const uint32_t mbar = sb;
    float* s_bias = (float*)(smem + 64);
    const int wid = tid >> 5;

    if (wid == 0) { TCGEN05_ALLOC(sb + 8, 256); TCGEN05_RELINQUISH(); }
    if (tid == 0) MBARRIER_INIT(mbar, 1);
    s_bias[tid] = bias[tid];
    __syncthreads();
    const uint32_t tmem = *(volatile uint32_t*)(smem + 8);

    const uint32_t tAh = sb + 4096;
    const uint32_t tAl = tAh + 16384;
    const uint32_t tBh = tAl + 16384;
    const uint32_t tBl = tBh + 32768;
    const uint64_t dAh = MAKE_SMEM_DESC(tAh);
    const uint64_t dAl = MAKE_SMEM_DESC(tAl);
    const uint64_t dBh = MAKE_SMEM_DESC(tBh);
    const uint64_t dBl = MAKE_SMEM_DESC(tBl);

    for (int c = 0; c < K / 32; c++) {
        const int k0 = c * 32;
        __syncthreads();
#pragma unroll
        for (int t = 0; t < 4; t++) {
            int idx = tid + t * 256;
            int row = idx >> 3, c4 = idx & 7;
            uint32_t sw = SMEM_SWIZZLE_128B((uint32_t)(row * 128 + c4 * 16));
            float4 v = *(const float4*)(A + (size_t)(bm + row) * K + k0 + c4 * 4);
            float4 h, l;
            h.x = to_tf32(v.x); l.x = to_tf32(v.x - h.x);
            h.y = to_tf32(v.y); l.y = to_tf32(v.y - h.y);
            h.z = to_tf32(v.z); l.z = to_tf32(v.z - h.z);
            h.w = to_tf32(v.w); l.w = to_tf32(v.w - h.w);
            *(float4*)(smem + (tAh - sb) + sw) = h;
            *(float4*)(smem + (tAl - sb) + sw) = l;
        }
#pragma unroll
        for (int t = 0; t < 8; t++) {
            int idx = tid + t * 256;
            int row = idx >> 3, c4 = idx & 7;
            uint32_t sw = SMEM_SWIZZLE_128B((uint32_t)(row * 128 + c4 * 16));
            float4 v = *(const float4*)(Bm + (size_t)row * K + k0 + c4 * 4);
            float4 h, l;
            h.x = to_tf32(v.x); l.x = to_tf32(v.x - h.x);
            h.y = to_tf32(v.y); l.y = to_tf32(v.y - h.y);
            h.z = to_tf32(v.z); l.z = to_tf32(v.z - h.z);
            h.w = to_tf32(v.w); l.w = to_tf32(v.w - h.w);
            *(float4*)(smem + (tBh - sb) + sw) = h;
            *(float4*)(smem + (tBl - sb) + sw) = l;
        }
        FENCE_PROXY_ASYNC_SHARED_CTA();
        __syncthreads();

        if (wid == 0 && elect_one_pred()) {
#pragma unroll
            for (int k = 0; k < 4; k++)
                TCGEN05_MMA_TF32_SS(tmem, dAh + k * 2, dBh + k * 2, IDESC_128x256,
                                    (c > 0) || (k > 0));
#pragma unroll
            for (int k = 0; k < 4; k++)
                TCGEN05_MMA_TF32_SS(tmem, dAh + k * 2, dBl + k * 2, IDESC_128x256, true);
#pragma unroll
            for (int k = 0; k < 4; k++)
                TCGEN05_MMA_TF32_SS(tmem, dAl + k * 2, dBh + k * 2, IDESC_128x256, true);
            TCGEN05_COMMIT(mbar);
        }
        MBARRIER_WAIT_PARITY(mbar, c & 1);
    }

    TCGEN05_FENCE_AFTER();

    if (wid < 4) {
        const int lane = tid & 31;
        const int mloc = wid * 32 + lane;
        const int m = bm + mloc;
#pragma unroll
        for (int g = 0; g < 8; g++) {
            uint32_t r[32];
            TCGEN05_LD_32X32B_X32(r, tmem + g * 32);
            TCGEN05_WAIT_LD();
            const int col0 = g * 32;
            if (mode == 0) {
#pragma unroll
                for (int j = 0; j < 32; j++)
                    r[j] = __float_as_uint(
                        to_tf32(__uint_as_float(r[j]) + s_bias[col0 + j]));
                float* blk = C + (((size_t)(m >> 7) * 8 + g) << 12);
#pragma unroll
                for (int j = 0; j < 8; j++) {
                    uint32_t sw = SMEM_SWIZZLE_128B((uint32_t)(mloc * 128 + j * 16));
                    *(float4*)((char*)blk + sw) = *(float4*)&r[j * 4];
                }
            } else {
#pragma unroll
                for (int j = 0; j < 32; j++)
                    r[j] = __float_as_uint(__uint_as_float(r[j]) + s_bias[col0 + j]);
                float* crow = C + (size_t)m * N;
#pragma unroll
                for (int j = 0; j < 8; j++)
                    *(float4*)&crow[col0 + j * 4] = *(float4*)&r[j * 4];
            }
        }
    }
    __syncthreads();
    if (wid == 0) TCGEN05_DEALLOC(tmem, 256);

#else
    // SIMT fallback
    constexpr int BK = 16, TM = 8, TN = 8;
    float* As = (float*)smem;
    float* Bs = As + BK * 128;
    const int tx = tid & 15, ty = tid >> 4;

    for (int nh = 0; nh < 2; nh++) {
        const int bn2 = nh * 128;
        float acc[TM][TN];
#pragma unroll
        for (int i = 0; i < TM; i++)
#pragma unroll
            for (int j = 0; j < TN; j++) acc[i][j] = 0.0f;

        for (int k0 = 0; k0 < K; k0 += BK) {
            __syncthreads();
#pragma unroll
            for (int i = 0; i < 2; i++) {
                int li = tid + i * 256;
                int row = li >> 2, kc = (li & 3) << 2;
                float4 va = *(const float4*)(A + (size_t)(bm + row) * K + k0 + kc);
                As[(kc + 0) * 128 + row] = va.x; As[(kc + 1) * 128 + row] = va.y;
                As[(kc + 2) * 128 + row] = va.z; As[(kc + 3) * 128 + row] = va.w;
                float4 vb = *(const float4*)(Bm + (size_t)(bn2 + row) * K + k0 + kc);
                Bs[(kc + 0) * 128 + row] = vb.x; Bs[(kc + 1) * 128 + row] = vb.y;
                Bs[(kc + 2) * 128 + row] = vb.z; Bs[(kc + 3) * 128 + row] = vb.w;
            }
            __syncthreads();
#pragma unroll
            for (int kk = 0; kk < BK; kk++) {
                float a[TM], bb[TN];
                *(float4*)&a[0]  = *(const float4*)&As[kk * 128 + ty * TM];
                *(float4*)&a[4]  = *(const float4*)&As[kk * 128 + ty * TM + 4];
                *(float4*)&bb[0] = *(const float4*)&Bs[kk * 128 + tx * TN];
                *(float4*)&bb[4] = *(const float4*)&Bs[kk * 128 + tx * TN + 4];
#pragma unroll
                for (int i = 0; i < TM; i++)
#pragma unroll
                    for (int j = 0; j < TN; j++)
                        acc[i][j] = fmaf(a[i], bb[j], acc[i][j]);
            }
        }
        const int row0 = bm + ty * TM, col0 = bn2 + tx * TN;
#pragma unroll
        for (int i = 0; i < TM; i++)
#pragma unroll
            for (int j = 0; j < TN; j++) {
                float v = acc[i][j] + bias[col0 + j];
                int m = row0 + i, n = col0 + j;
                if (mode == 0)
                    C[qk_blk_off(m >> 7, n >> 5, m & 127, n & 31)] = to_tf32(v);
                else
                    C[(size_t)m * N + n] = v;
            }
        __syncthreads();
    }
#endif
}

// ---------------------------------------------------------------------------
// Scores GEMM: E[b,m,n] = exp((q.k)/16) * maskfac(n)  stored bf16,
// plus row-sum partials rpart[nx][b][m].
// BM=256 (dual TMEM accumulators), BN=256, 3-stage cp.async.bulk pipeline.
// smem: [0,48) mbars: full[3] @0/8/16, empty[3] @24/32/40, done @48
//       [56,60) tmem, [64,1088) maskfac[256] floats
//       [4096..) 3 stages x {A0 16K | A1 16K | B 32K} = 196608
// ---------------------------------------------------------------------------
static constexpr int SC_STAGE = 65536;
static constexpr int SC_SMEM = 4096 + 3 * SC_STAGE;   // 200704

__global__ __launch_bounds__(256)
void score_gemm(const float* __restrict__ Qb, const float* __restrict__ Kb,
                const int* __restrict__ mask, __nv_bfloat16* __restrict__ E,
                float* __restrict__ rpart, float scale)
{
    extern __shared__ __align__(1024) char smem[];
    const int tid = threadIdx.x;
    const int bz = blockIdx.z;
    __nv_bfloat16* C = E + (size_t)bz * kS * kS;
    const int* mk = mask + (size_t)bz * kS;

    const int my = blockIdx.y;          // m tile (256 rows)
    const int nx = blockIdx.x;          // n tile (256 cols)
    const int bm = my * 256;
    const int bn = nx * 256;

#if HAS_TCGEN05
    const uint32_t sb = smem_to_u32_gen(smem);
    const uint32_t m_done = sb + 48;
    float* s_mf = (float*)(smem + 64);
    const int wid = tid >> 5;

    if (wid == 0) { TCGEN05_ALLOC(sb + 56, 512); TCGEN05_RELINQUISH(); }
    if (tid == 0) {
#pragma unroll
        for (int s = 0; s < 3; s++) {
            MBARRIER_INIT(sb + s * 8, 1);        // full[s]
            MBARRIER_INIT(sb + 24 + s * 8, 1);   // empty[s]
        }
        MBARRIER_INIT(m_done, 1);
    }
    s_mf[tid] = (mk[bn + tid] != 0) ? 1.0f : 0.0f;
    __syncthreads();
    const uint32_t tmem = *(volatile uint32_t*)(smem + 56);

    uint64_t dA0[3], dA1[3], dB[3];
#pragma unroll
    for (int s = 0; s < 3; s++) {
        uint32_t base = sb + 4096 + s * SC_STAGE;
        dA0[s] = MAKE_SMEM_DESC(base);
        dA1[s] = MAKE_SMEM_DESC(base + 16384);
        dB[s]  = MAKE_SMEM_DESC(base + 32768);
    }

    // global 128-row block indices
    const int amt0 = bz * 16 + my * 2;       // A blocks (2)
    const int bmt0 = bz * 16 + nx * 2;       // B blocks (2)

    if (wid == 1) {
        if (elect_one_pred()) {
            for (int c = 0; c < 8; c++) {
                const int s = c % 3;
                const int w = c / 3;
                const uint32_t m_full = sb + s * 8;
                const uint32_t m_emp  = sb + 24 + s * 8;
                const uint32_t st = sb + 4096 + s * SC_STAGE;
                MBARRIER_WAIT_PARITY(m_emp, 1 ^ (w & 1));
                MBARRIER_EXPECT_TX(m_full, SC_STAGE);
                CP_ASYNC_BULK(st,
                              Qb + (((size_t)amt0 * 8 + c) << 12), 16384, m_full);
                CP_ASYNC_BULK(st + 16384,
                              Qb + (((size_t)(amt0 + 1) * 8 + c) << 12), 16384, m_full);
                CP_ASYNC_BULK(st + 32768,
                              Kb + (((size_t)bmt0 * 8 + c) << 12), 16384, m_full);
                CP_ASYNC_BULK(st + 49152,
                              Kb + (((size_t)(bmt0 + 1) * 8 + c) << 12), 16384, m_full);
            }
        }
    } else if (wid == 0) {
        if (elect_one_pred()) {
            for (int c = 0; c < 8; c++) {
                const int s = c % 3;
                const int w = c / 3;
                const uint32_t m_full = sb + s * 8;
                const uint32_t m_emp  = sb + 24 + s * 8;
                MBARRIER_WAIT_PARITY(m_full, w & 1);
#pragma unroll
                for (int k = 0; k < 4; k++)
                    TCGEN05_MMA_TF32_SS(tmem, dA0[s] + k * 2, dB[s] + k * 2,
                                        IDESC_128x256, (c > 0) || (k > 0));
#pragma unroll
                for (int k = 0; k < 4; k++)
                    TCGEN05_MMA_TF32_SS(tmem + 256, dA1[s] + k * 2, dB[s] + k * 2,
                                        IDESC_128x256, (c > 0) || (k > 0));
                TCGEN05_COMMIT(m_emp);
            }
            TCGEN05_COMMIT(m_done);
        }
    }

    MBARRIER_WAIT_PARITY(m_done, 0);
    TCGEN05_FENCE_AFTER();

    // Epilogue: warps 0-3 -> D0 (rows bm..+127), warps 4-7 -> D1 (+128)
    {
        const int lane = tid & 31;
        const int half = wid >> 2;
        const int m = bm + half * 128 + (wid & 3) * 32 + lane;
        const uint32_t tbase = tmem + half * 256;
        __nv_bfloat16* crow = C + (size_t)m * kS + bn;
        float rs = 0.0f;
#pragma unroll
        for (int g = 0; g < 8; g++) {
            uint32_t r[32];
            TCGEN05_LD_32X32B_X32(r, tbase + g * 32);
            TCGEN05_WAIT_LD();
            const int col0 = g * 32;
            float e[32];
#pragma unroll
            for (int j = 0; j < 32; j++) {
                e[j] = __expf(__uint_as_float(r[j]) * scale) * s_mf[col0 + j];
                rs += e[j];
            }
            uint32_t pk[16];
#pragma unroll
            for (int j = 0; j < 16; j++)
                pk[j] = pack_bf16x2(e[j * 2], e[j * 2 + 1]);
#pragma unroll
            for (int j = 0; j < 4; j++)
                *(uint4*)&crow[col0 + j * 8] = *(uint4*)&pk[j * 4];
        }
        rpart[((size_t)nx * kB + bz) * kS + m] = rs;
    }
    __syncthreads();
    if (wid == 0) TCGEN05_DEALLOC(tmem, 512);

#else
    // SIMT fallback — reads blocked Q/K layout, writes bf16 E + rpart.
    constexpr int BK = 16, TM = 8, TN = 8;
    float* As = (float*)smem;
    float* Bs = As + BK * 128;
    const int tx = tid & 15, ty = tid >> 4;
    const int amt0 = bz * 16 + my * 2;
    const int bmt0 = bz * 16 + nx * 2;

    for (int mh = 0; mh < 2; mh++) {
        const int amt = amt0 + mh;
        float rs[TM];
#pragma unroll
        for (int i = 0; i < TM; i++) rs[i] = 0.0f;

        for (int nh = 0; nh < 2; nh++) {
            const int bmtl = bmt0 + nh;
            float acc[TM][TN];
#pragma unroll
            for (int i = 0; i < TM; i++)
#pragma unroll
                for (int j = 0; j < TN; j++) acc[i][j] = 0.0f;

            for (int k0 = 0; k0 < kD; k0 += BK) {
                __syncthreads();
                for (int li = tid; li < 128 * BK; li += 256) {
                    int row = li / BK, kc = li % BK;
                    As[kc * 128 + row] =
                        Qb[qk_blk_off(amt, (k0 + kc) >> 5, row, (k0 + kc) & 31)];
                    Bs[kc * 128 + row] =
                        Kb[qk_blk_off(bmtl, (k0 + kc) >> 5, row, (k0 + kc) & 31)];
                }
                __syncthreads();
#pragma unroll
                for (int kk = 0; kk < BK; kk++) {
                    float a[TM], bb[TN];
                    *(float4*)&a[0]  = *(const float4*)&As[kk * 128 + ty * TM];
                    *(float4*)&a[4]  = *(const float4*)&As[kk * 128 + ty * TM + 4];
                    *(float4*)&bb[0] = *(const float4*)&Bs[kk * 128 + tx * TN];
                    *(float4*)&bb[4] = *(const float4*)&Bs[kk * 128 + tx * TN + 4];
#pragma unroll
                    for (int i = 0; i < TM; i++)
#pragma unroll
                        for (int j = 0; j < TN; j++)
                            acc[i][j] = fmaf(a[i], bb[j], acc[i][j]);
                }
            }
            const int row0 = bm + mh * 128 + ty * TM;
            const int col0 = bn + nh * 128 + tx * TN;
#pragma unroll
            for (int i = 0; i < TM; i++)
#pragma unroll
                for (int j = 0; j < TN; j++) {
                    float e = __expf(acc[i][j] * scale)
                              * ((mk[col0 + j] != 0) ? 1.0f : 0.0f);
                    C[(size_t)(row0 + i) * kS + col0 + j] = __float2bfloat16(e);
                    rs[i] += e;
                }
            __syncthreads();
        }
#pragma unroll
        for (int i = 0; i < TM; i++) {
            float v = rs[i];
#pragma unroll
            for (int o = 8; o; o >>= 1) v += __shfl_xor_sync(0xffffffffu, v, o);
            if (tx == 0)
                rpart[((size_t)nx * kB + bz) * kS + bm + mh * 128 + ty * TM + i] = v;
        }
    }
#endif
}

// ---------------------------------------------------------------------------
// invr[b,q] = 1 / sum_nx rpart[nx][b][q]
// ---------------------------------------------------------------------------
__global__ __launch_bounds__(256)
void rowsum_reduce_kernel(const float* __restrict__ rpart, float* __restrict__ invr)
{
    const int i = blockIdx.x * 256 + threadIdx.x;
    float s = 0.0f;
#pragma unroll
    for (int c = 0; c < NXT; c++) s += rpart[(size_t)c * (kB * kS) + i];
    invr[i] = 1.0f / s;
}

// ---------------------------------------------------------------------------
// Column-sum stream over bf16 E: wpart += E[b,q,k] * invr[b,q]. No barriers.
// ---------------------------------------------------------------------------
__global__ __launch_bounds__(256)
void colsum_stream_kernel(const __nv_bfloat16* __restrict__ E,
                          const float* __restrict__ invr,
                          float* __restrict__ wpart)
{
    const int ch = blockIdx.x;
    const int b  = blockIdx.y;
    const int tid = threadIdx.x;
    const __nv_bfloat16* base = E + ((size_t)b * kS + (size_t)ch * 32) * kS;
    const float* iv = invr + (size_t)b * kS + (size_t)ch * 32;

    float wacc[8];
#pragma unroll
    for (int i = 0; i < 8; i++) wacc[i] = 0.0f;

    for (int r = 0; r < 32; r++) {
        const float s = iv[r];
        const __nv_bfloat16* p = base + (size_t)r * kS + tid * 8;
        uint4 v = *(const uint4*)p;     // 8 bf16
        const uint32_t pk[4] = {v.x, v.y, v.z, v.w};
#pragma unroll
        for (int i = 0; i < 4; i++) {
            float2 f = __bfloat1622float2(*(const __nv_bfloat162*)&pk[i]);
            wacc[i * 2]     = fmaf(f.x, s, wacc[i * 2]);
            wacc[i * 2 + 1] = fmaf(f.y, s, wacc[i * 2 + 1]);
        }
    }

    float* o = wpart + (size_t)ch * (kB * kS) + (size_t)b * kS + tid * 8;
    *(float4*)&o[0] = make_float4(wacc[0], wacc[1], wacc[2], wacc[3]);
    *(float4*)&o[4] = make_float4(wacc[4], wacc[5], wacc[6], wacc[7]);
}

__global__ __launch_bounds__(256)
void colsum_reduce_kernel(const float* __restrict__ wpart, float* __restrict__ w)
{
    const int i = blockIdx.x * 256 + threadIdx.x;
    float s = 0.0f;
#pragma unroll
    for (int c = 0; c < QCH; c++) s += wpart[(size_t)c * (kB * kS) + i];
    w[i] = s;
}

__global__ __launch_bounds__(256)
void out_part_kernel(const float* __restrict__ w, const float* __restrict__ V,
                     float* __restrict__ opart)
{
    const int chunk = blockIdx.x;
    const int b     = blockIdx.y;
    const int d     = threadIdx.x;
    const float* vb = V + ((size_t)b * kS + (size_t)chunk * 64) * kD;
    const float* wb = w + b * kS + chunk * 64;
    float s = 0.0f;
#pragma unroll
    for (int k = 0; k < 64; k++) s = fmaf(wb[k], vb[(size_t)k * kD + d], s);
    opart[(size_t)(chunk * kB + b) * kD + d] = s;
}

__global__ __launch_bounds__(256)
void out_reduce_kernel(const float* __restrict__ opart, float* __restrict__ out)
{
    const int i = blockIdx.x * 256 + threadIdx.x;
    float s = 0.0f;
#pragma unroll
    for (int c = 0; c < N_KCHUNK; c++) s += opart[(size_t)c * (kB * kD) + i];
    out[i] = s * (1.0f / (float)kS);
}

// ---------------------------------------------------------------------------
// Launch
// ---------------------------------------------------------------------------
extern "C" void kernel_launch(void* const* d_in, const int* in_sizes, int n_in,
                              void* d_out, int out_size)
{
    const float* nodes = (const float*)d_in[0];
    const int*   mask  = (const int*)  d_in[1];
    const float* Wq    = (const float*)d_in[2];
    const float* bq    = (const float*)d_in[3];
    const float* Wk    = (const float*)d_in[4];
    const float* bk    = (const float*)d_in[5];
    const float* Wv    = (const float*)d_in[6];
    const float* bv    = (const float*)d_in[7];
    float* out = (float*)d_out;

    float *Qb, *Kb, *V, *rpart, *invr, *w, *wpart, *opart;
    __nv_bfloat16* E;
    cudaGetSymbolAddress((void**)&Qb,    g_Qb);
    cudaGetSymbolAddress((void**)&Kb,    g_Kb);
    cudaGetSymbolAddress((void**)&V,     g_V);
    cudaGetSymbolAddress((void**)&E,     g_E);
    cudaGetSymbolAddress((void**)&rpart, g_rpart);
    cudaGetSymbolAddress((void**)&invr,  g_invr);
    cudaGetSymbolAddress((void**)&w,     g_w);
    cudaGetSymbolAddress((void**)&wpart, g_wpart);
    cudaGetSymbolAddress((void**)&opart, g_opart);

    cudaFuncSetAttribute(proj_gemm,
                         cudaFuncAttributeMaxDynamicSharedMemorySize, PROJ_SMEM);
    cudaFuncSetAttribute(score_gemm,
                         cudaFuncAttributeMaxDynamicSharedMemorySize, SC_SMEM);

    dim3 blk(256);

    // 1. All three projections in one launch (3xTF32, 384 CTAs).
    dim3 gproj(3, kM / 128, 1);
    proj_gemm<<<gproj, blk, PROJ_SMEM>>>(nodes, Wq, Wk, Wv, bq, bk, bv,
                                         Qb, Kb, V);

    // 2. Scores -> E = exp(score/16) bf16 (masked = 0) + rowsum partials
    dim3 gsc(kS / 256, kS / 256, kB);
    score_gemm<<<gsc, blk, SC_SMEM>>>(Qb, Kb, mask, E, rpart, 0.0625f);

    // 3. rowsum -> invr, stream colsum, reduce, output contraction
    rowsum_reduce_kernel<<<(kB * kS) / 256, blk>>>(rpart, invr);
    colsum_stream_kernel<<<dim3(QCH, kB), blk>>>(E, invr, wpart);
    colsum_reduce_kernel<<<(kB * kS) / 256, blk>>>(wpart, w);
    out_part_kernel<<<dim3(N_KCHUNK, kB), blk>>>(w, V, opart);
    out_reduce_kernel<<<(kB * kD) / 256, blk>>>(opart, out);
}

// round 10
// speedup vs baseline: 1.9685x; 1.1708x over previous
#include <cuda_runtime.h>
#include <cuda_bf16.h>
#include <cstdint>
#include <math.h>

// ---------------------------------------------------------------------------
// Problem constants
// ---------------------------------------------------------------------------
static constexpr int kB = 8;
static constexpr int kS = 2048;
static constexpr int kD = 256;
static constexpr int kM = kB * kS;
static constexpr int QCH = 64;       // colsum: 32 rows per chunk
static constexpr int N_KCHUNK = 32;  // output split over keys
static constexpr int NXT = kS / 256; // 8 n-tiles per batch row

// Scratch (static device memory)
// Blocked layout: block = [128 rows x 32 cols] = 16KB, SW128-swizzled.
// Block id within a tensor = gmtile*8 + kchunk.
__device__ float g_Nb[kM * kD];                        // tf32-rounded nodes, blocked
__device__ float g_Wh[3 * kD * kD];                    // weight hi, blocked (q,k,v)
__device__ float g_Wl[2 * kD * kD];                    // weight lo, blocked (q,k)
__device__ float g_Qb[kB * kS * kD];                   // tf32 q, blocked
__device__ float g_Kb[kB * kS * kD];                   // tf32 k, blocked
__device__ float g_V[kB * kS * kD];                    // fp32 v, row-major
__device__ __nv_bfloat16 g_E[(size_t)kB * kS * kS];    // exp scores (bf16)
__device__ float g_rpart[NXT * kB * kS];
__device__ float g_invr[kB * kS];
__device__ float g_w[kB * kS];
__device__ float g_wpart[QCH * kB * kS];
__device__ float g_opart[N_KCHUNK * kB * kD];

#if defined(__CUDA_ARCH__) && defined(__CUDA_ARCH_FEAT_SM103_ALL)
#define HAS_TCGEN05 1
#else
#define HAS_TCGEN05 0
#endif

#define SMEM_SWIZZLE_128B(byte_offset) \
    ((byte_offset) ^ (((byte_offset) >> 3) & 0x70))

__device__ __forceinline__ uint32_t smem_to_u32_gen(const void* p) {
    uint32_t a;
    asm("{ .reg .u64 t; cvta.to.shared.u64 t, %1; cvt.u32.u64 %0, t; }"
        : "=r"(a) : "l"(p));
    return a;
}

__device__ __forceinline__ float to_tf32(float x) {
    float y;
    asm("cvt.rna.tf32.f32 %0, %1;" : "=f"(y) : "f"(x));
    return y;
}

__device__ __forceinline__ uint32_t pack_bf16x2(float lo, float hi) {
    uint32_t r;
    asm("cvt.rn.bf16x2.f32 %0, %1, %2;" : "=r"(r) : "f"(hi), "f"(lo));
    return r;
}

// float-index offset of element (r in [0,128), c in [0,32)) in blocked layout
__device__ __forceinline__ size_t qk_blk_off(int gmtile, int kchunk, int r, int c) {
    uint32_t byte = (uint32_t)(r * 128 + (c >> 2) * 16);
    uint32_t sw = SMEM_SWIZZLE_128B(byte) + (uint32_t)(c & 3) * 4;
    return ((size_t)(gmtile * 8 + kchunk) << 12) + (sw >> 2);
}

#if HAS_TCGEN05
__device__ __forceinline__ uint32_t elect_one_pred() {
    uint32_t pred;
    asm volatile(
        "{\n\t.reg .pred p;\n\t"
        "elect.sync _|p, 0xFFFFFFFF;\n\t"
        "selp.b32 %0, 1, 0, p;\n\t}"
        : "=r"(pred));
    return pred;
}

#define TCGEN05_ALLOC(smem_result_addr, nCols) \
    asm volatile("tcgen05.alloc.cta_group::1.sync.aligned.shared::cta.b32 [%0], %1;" \
                 :: "r"((uint32_t)(smem_result_addr)), "r"((uint32_t)(nCols)) : "memory")
#define TCGEN05_DEALLOC(tmem_addr, nCols) \
    asm volatile("tcgen05.dealloc.cta_group::1.sync.aligned.b32 %0, %1;" \
                 :: "r"(tmem_addr), "r"((uint32_t)(nCols)))
#define TCGEN05_RELINQUISH() \
    asm volatile("tcgen05.relinquish_alloc_permit.cta_group::1.sync.aligned;")
#define TCGEN05_COMMIT(mbar_smem_addr) \
    asm volatile("tcgen05.commit.cta_group::1.mbarrier::arrive::one.shared::cluster.b64 [%0];" \
                 :: "r"((uint32_t)(mbar_smem_addr)) : "memory")
#define TCGEN05_FENCE_AFTER() \
    asm volatile("tcgen05.fence::after_thread_sync;" ::: "memory")
#define TCGEN05_WAIT_LD() \
    asm volatile("tcgen05.wait::ld.sync.aligned;" ::: "memory")
#define MBARRIER_INIT(mbar_smem_addr, count) \
    asm volatile("mbarrier.init.shared.b64 [%0], %1;" \
                 :: "r"((uint32_t)(mbar_smem_addr)), "r"((uint32_t)(count)) : "memory")
#define MBARRIER_EXPECT_TX(mbar_smem_addr, tx_bytes) \
    asm volatile("mbarrier.arrive.expect_tx.shared.b64 _, [%0], %1;" \
                 :: "r"((uint32_t)(mbar_smem_addr)), "r"((uint32_t)(tx_bytes)) : "memory")
#define FENCE_PROXY_ASYNC_SHARED_CTA() \
    asm volatile("fence.proxy.async.shared::cta;" ::: "memory")

#define MBARRIER_WAIT_PARITY(mbar_smem_addr, phase_parity) do { \
    uint32_t _mbar = (uint32_t)(mbar_smem_addr); \
    uint32_t _parity = (uint32_t)(phase_parity); \
    uint32_t _done; \
    asm volatile( \
        "{\n\t.reg .pred p;\n\t" \
        "mbarrier.try_wait.parity.acquire.cta.shared::cta.b64 p, [%1], %2;\n\t" \
        "selp.b32 %0, 1, 0, p;\n\t}" \
        : "=r"(_done) : "r"(_mbar), "r"(_parity) : "memory"); \
    if (!_done) { \
        asm volatile( \
            "{\n\t.reg .pred P1;\n\t" \
            "WAIT_LOOP_%=:\n\t" \
            "mbarrier.try_wait.parity.acquire.cta.shared::cta.b64 P1, [%0], %1, 0x989680;\n\t" \
            "@P1 bra.uni WAIT_DONE_%=;\n\t" \
            "bra.uni WAIT_LOOP_%=;\n\t" \
            "WAIT_DONE_%=:\n\t}" \
            :: "r"(_mbar), "r"(_parity) : "memory"); \
    } \
} while(0)

#define TCGEN05_LD_32X32B_X32(r, tmem_addr) \
    asm volatile( \
        "tcgen05.ld.sync.aligned.32x32b.x32.b32 " \
        "{%0, %1, %2, %3, %4, %5, %6, %7, " \
        " %8, %9, %10, %11, %12, %13, %14, %15, " \
        " %16, %17, %18, %19, %20, %21, %22, %23, " \
        " %24, %25, %26, %27, %28, %29, %30, %31}, [%32];" \
        : "=r"((r)[0]),  "=r"((r)[1]),  "=r"((r)[2]),  "=r"((r)[3]), \
          "=r"((r)[4]),  "=r"((r)[5]),  "=r"((r)[6]),  "=r"((r)[7]), \
          "=r"((r)[8]),  "=r"((r)[9]),  "=r"((r)[10]), "=r"((r)[11]), \
          "=r"((r)[12]), "=r"((r)[13]), "=r"((r)[14]), "=r"((r)[15]), \
          "=r"((r)[16]), "=r"((r)[17]), "=r"((r)[18]), "=r"((r)[19]), \
          "=r"((r)[20]), "=r"((r)[21]), "=r"((r)[22]), "=r"((r)[23]), \
          "=r"((r)[24]), "=r"((r)[25]), "=r"((r)[26]), "=r"((r)[27]), \
          "=r"((r)[28]), "=r"((r)[29]), "=r"((r)[30]), "=r"((r)[31]) \
        : "r"(tmem_addr))

#define TCGEN05_MMA_TF32_SS(d_tmem, a_desc, b_desc, idesc, enable_d) do { \
    uint32_t _en = (enable_d) ? 1u : 0u; \
    uint32_t _zero = 0u; \
    asm volatile( \
        "{\n\t.reg .pred p;\n\t" \
        "setp.ne.u32 p, %5, 0;\n\t" \
        "tcgen05.mma.cta_group::1.kind::tf32 [%0], %1, %2, %3, {%4, %4, %4, %4}, p;\n\t" \
        "}" \
        :: "r"(d_tmem), "l"(a_desc), "l"(b_desc), "r"(idesc), "r"(_zero), "r"(_en) \
        : "memory"); \
} while(0)

static constexpr uint64_t SMEM_DESC_BASE_SW128 =
    (uint64_t(2)  << 61) | (uint64_t(1) << 46) | (uint64_t(64) << 32) | (uint64_t(1) << 16);
#define MAKE_SMEM_DESC(base_addr) \
    (SMEM_DESC_BASE_SW128 | ((uint64_t)((base_addr) >> 4) & 0x3FFF))

#define CP_ASYNC_BULK(dst_smem, src_gmem, bytes, mbar) \
    asm volatile("cp.async.bulk.shared::cta.global.mbarrier::complete_tx::bytes " \
                 "[%0], [%1], %2, [%3];" \
                 :: "r"((uint32_t)(dst_smem)), "l"(src_gmem), \
                    "r"((uint32_t)(bytes)), "r"((uint32_t)(mbar)) : "memory")

// IDESC for tf32, F32 accum, M=128, N=256
static constexpr uint32_t IDESC_128x256 =
    (1u << 4) | (2u << 7) | (2u << 10) | ((256 / 8) << 17) | ((128 / 16) << 24);
#endif  // HAS_TCGEN05

// ---------------------------------------------------------------------------
// Prep 1: nodes -> tf32-rounded, blocked-swizzled. grid (8, kM/128).
// ---------------------------------------------------------------------------
__global__ __launch_bounds__(256)
void nodes_prep(const float* __restrict__ src, float* __restrict__ Nb)
{
    const int kc = blockIdx.x;
    const int mt = blockIdx.y;
    const int tid = threadIdx.x;
    float* blk = Nb + (((size_t)mt * 8 + kc) << 12);
#pragma unroll
    for (int t = 0; t < 4; t++) {
        int idx = tid + t * 256;
        int row = idx >> 3, c4 = idx & 7;
        float4 v = *(const float4*)(src + (size_t)(mt * 128 + row) * kD + kc * 32 + c4 * 4);
        v.x = to_tf32(v.x); v.y = to_tf32(v.y);
        v.z = to_tf32(v.z); v.w = to_tf32(v.w);
        uint32_t sw = SMEM_SWIZZLE_128B((uint32_t)(row * 128 + c4 * 16));
        *(float4*)((char*)blk + sw) = v;
    }
}

// ---------------------------------------------------------------------------
// Prep 2: weights -> (hi, lo) tf32 split, blocked. grid (8, 2, 3).
// Wh holds q,k,v hi; Wl holds q,k lo (V uses hi only).
// ---------------------------------------------------------------------------
__global__ __launch_bounds__(256)
void wsplit_prep(const float* __restrict__ Wq, const float* __restrict__ Wk,
                 const float* __restrict__ Wv,
                 float* __restrict__ Wh, float* __restrict__ Wl)
{
    const int kc = blockIdx.x;
    const int mt = blockIdx.y;
    const int w  = blockIdx.z;
    const int tid = threadIdx.x;
    const float* W = (w == 0) ? Wq : (w == 1) ? Wk : Wv;
    float* bh = Wh + (size_t)w * (kD * kD) + (((size_t)mt * 8 + kc) << 12);
    float* bl = (w < 2) ? Wl + (size_t)w * (kD * kD) + (((size_t)mt * 8 + kc) << 12)
                        : nullptr;
#pragma unroll
    for (int t = 0; t < 4; t++) {
        int idx = tid + t * 256;
        int row = idx >> 3, c4 = idx & 7;
        float4 v = *(const float4*)(W + (size_t)(mt * 128 + row) * kD + kc * 32 + c4 * 4);
        float4 h, l;
        h.x = to_tf32(v.x); l.x = to_tf32(v.x - h.x);
        h.y = to_tf32(v.y); l.y = to_tf32(v.y - h.y);
        h.z = to_tf32(v.z); l.z = to_tf32(v.z - h.z);
        h.w = to_tf32(v.w); l.w = to_tf32(v.w - h.w);
        uint32_t sw = SMEM_SWIZZLE_128B((uint32_t)(row * 128 + c4 * 16));
        *(float4*)((char*)bh + sw) = h;
        if (bl) *(float4*)((char*)bl + sw) = l;
    }
}

// ---------------------------------------------------------------------------
// Pipelined projection GEMM.
//   q/k (bx<2): C = tf32( A_h @ (W_h + W_l)^T + bias )  -> blocked layout
//   v  (bx=2): C = A_h @ W_h^T + bias                   -> row-major fp32
// BM=256 (dual TMEM accumulators), BN=256, 2-stage cp.async.bulk pipeline.
// smem ctrl: full[2]@0/8, empty[2]@16/24, done@32, tmem@40, bias[256]@64
// stage (96KB): A0 16K | A1 16K | Bh 32K | Bl 32K
// ---------------------------------------------------------------------------
static constexpr int PJ_STAGE = 98304;
static constexpr int PJ_SMEM = 4096 + 2 * PJ_STAGE;   // 200704

__global__ __launch_bounds__(256)
void proj_gemm(const float* __restrict__ Nb,
               const float* __restrict__ Wh, const float* __restrict__ Wl,
               const float* __restrict__ b0, const float* __restrict__ b1,
               const float* __restrict__ b2,
               float* __restrict__ C0, float* __restrict__ C1,
               float* __restrict__ C2)
{
    extern __shared__ __align__(1024) char smem[];
    const int tid = threadIdx.x;
    const int bx = blockIdx.x;           // 0=q, 1=k, 2=v
    const int by = blockIdx.y;           // m tile of 256 rows
    const float* bias = (bx == 0) ? b0 : (bx == 1) ? b1 : b2;
    float* C = (bx == 0) ? C0 : (bx == 1) ? C1 : C2;
    const bool two_pass = (bx < 2);
    const float* WhB = Wh + (size_t)bx * (kD * kD);
    const float* WlB = Wl + (size_t)bx * (kD * kD);   // unused for bx==2

#if HAS_TCGEN05
    const uint32_t sb = smem_to_u32_gen(smem);
    const uint32_t m_done = sb + 32;
    float* s_bias = (float*)(smem + 64);
    const int wid = tid >> 5;

    if (wid == 0) { TCGEN05_ALLOC(sb + 40, 512); TCGEN05_RELINQUISH(); }
    if (tid == 0) {
        MBARRIER_INIT(sb + 0, 1);   // full0
        MBARRIER_INIT(sb + 8, 1);   // full1
        MBARRIER_INIT(sb + 16, 1);  // empty0
        MBARRIER_INIT(sb + 24, 1);  // empty1
        MBARRIER_INIT(m_done, 1);
    }
    s_bias[tid] = bias[tid];
    __syncthreads();
    const uint32_t tmem = *(volatile uint32_t*)(smem + 40);

    uint64_t dA0[2], dA1[2], dBh[2], dBl[2];
#pragma unroll
    for (int s = 0; s < 2; s++) {
        uint32_t base = sb + 4096 + s * PJ_STAGE;
        dA0[s] = MAKE_SMEM_DESC(base);
        dA1[s] = MAKE_SMEM_DESC(base + 16384);
        dBh[s] = MAKE_SMEM_DESC(base + 32768);
        dBl[s] = MAKE_SMEM_DESC(base + 65536);
    }

    const int amt0 = by * 2;   // A block mtiles
    const uint32_t tx_bytes = two_pass ? 98304u : 65536u;

    if (wid == 1) {
        if (elect_one_pred()) {
            for (int c = 0; c < 8; c++) {
                const int s = c & 1;
                const int i = c >> 1;
                const uint32_t m_full = sb + s * 8;
                const uint32_t m_emp  = sb + 16 + s * 8;
                const uint32_t st = sb + 4096 + s * PJ_STAGE;
                MBARRIER_WAIT_PARITY(m_emp, 1 ^ (i & 1));
                MBARRIER_EXPECT_TX(m_full, tx_bytes);
                CP_ASYNC_BULK(st,
                              Nb + (((size_t)amt0 * 8 + c) << 12), 16384, m_full);
                CP_ASYNC_BULK(st + 16384,
                              Nb + (((size_t)(amt0 + 1) * 8 + c) << 12), 16384, m_full);
                CP_ASYNC_BULK(st + 32768,
                              WhB + ((size_t)c << 12), 16384, m_full);
                CP_ASYNC_BULK(st + 49152,
                              WhB + (((size_t)(8 + c)) << 12), 16384, m_full);
                if (two_pass) {
                    CP_ASYNC_BULK(st + 65536,
                                  WlB + ((size_t)c << 12), 16384, m_full);
                    CP_ASYNC_BULK(st + 81920,
                                  WlB + (((size_t)(8 + c)) << 12), 16384, m_full);
                }
            }
        }
    } else if (wid == 0) {
        if (elect_one_pred()) {
            for (int c = 0; c < 8; c++) {
                const int s = c & 1;
                const int i = c >> 1;
                const uint32_t m_full = sb + s * 8;
                const uint32_t m_emp  = sb + 16 + s * 8;
                MBARRIER_WAIT_PARITY(m_full, i & 1);
#pragma unroll
                for (int k = 0; k < 4; k++) {
                    TCGEN05_MMA_TF32_SS(tmem, dA0[s] + k * 2, dBh[s] + k * 2,
                                        IDESC_128x256, (c > 0) || (k > 0));
                    TCGEN05_MMA_TF32_SS(tmem + 256, dA1[s] + k * 2, dBh[s] + k * 2,
                                        IDESC_128x256, (c > 0) || (k > 0));
                }
                if (two_pass) {
#pragma unroll
                    for (int k = 0; k < 4; k++) {
                        TCGEN05_MMA_TF32_SS(tmem, dA0[s] + k * 2, dBl[s] + k * 2,
                                            IDESC_128x256, true);
                        TCGEN05_MMA_TF32_SS(tmem + 256, dA1[s] + k * 2, dBl[s] + k * 2,
                                            IDESC_128x256, true);
                    }
                }
                TCGEN05_COMMIT(m_emp);
            }
            TCGEN05_COMMIT(m_done);
        }
    }

    MBARRIER_WAIT_PARITY(m_done, 0);
    TCGEN05_FENCE_AFTER();

    // Epilogue: warps 0-3 -> D0 (rows 0..127), warps 4-7 -> D1 (+128)
    {
        const int lane = tid & 31;
        const int half = wid >> 2;
        const int mloc = (wid & 3) * 32 + lane;       // row within 128-tile
        const int m = by * 256 + half * 128 + mloc;
        const uint32_t tbase = tmem + half * 256;
#pragma unroll
        for (int g = 0; g < 8; g++) {
            uint32_t r[32];
            TCGEN05_LD_32X32B_X32(r, tbase + g * 32);
            TCGEN05_WAIT_LD();
            const int col0 = g * 32;
            if (two_pass) {
#pragma unroll
                for (int j = 0; j < 32; j++)
                    r[j] = __float_as_uint(
                        to_tf32(__uint_as_float(r[j]) + s_bias[col0 + j]));
                float* blk = C + (((size_t)(m >> 7) * 8 + g) << 12);
#pragma unroll
                for (int j = 0; j < 8; j++) {
                    uint32_t sw = SMEM_SWIZZLE_128B((uint32_t)(mloc * 128 + j * 16));
                    *(float4*)((char*)blk + sw) = *(float4*)&r[j * 4];
                }
            } else {
#pragma unroll
                for (int j = 0; j < 32; j++)
                    r[j] = __float_as_uint(__uint_as_float(r[j]) + s_bias[col0 + j]);
                float* crow = C + (size_t)m * kD;
#pragma unroll
                for (int j = 0; j < 8; j++)
                    *(float4*)&crow[col0 + j * 4] = *(float4*)&r[j * 4];
            }
        }
    }
    __syncthreads();
    if (wid == 0) TCGEN05_DEALLOC(tmem, 512);

#else
    // SIMT fallback — reads blocked Nb / Wh / Wl.
    constexpr int BK = 16, TM = 8, TN = 8;
    float* As = (float*)smem;
    float* Bs = As + BK * 128;
    const int tx = tid & 15, ty = tid >> 4;

    for (int mh = 0; mh < 2; mh++) {
        const int amt = by * 2 + mh;
        for (int nh = 0; nh < 2; nh++) {
            float acc[TM][TN];
#pragma unroll
            for (int i = 0; i < TM; i++)
#pragma unroll
                for (int j = 0; j < TN; j++) acc[i][j] = 0.0f;

            for (int k0 = 0; k0 < kD; k0 += BK) {
                __syncthreads();
                for (int li = tid; li < 128 * BK; li += 256) {
                    int row = li / BK, kc = li % BK;
                    size_t off = qk_blk_off(nh, (k0 + kc) >> 5, row, (k0 + kc) & 31);
                    As[kc * 128 + row] =
                        Nb[qk_blk_off(amt, (k0 + kc) >> 5, row, (k0 + kc) & 31)];
                    float bw = WhB[off];
                    if (two_pass) bw += WlB[off];
                    Bs[kc * 128 + row] = bw;
                }
                __syncthreads();
#pragma unroll
                for (int kk = 0; kk < BK; kk++) {
                    float a[TM], bb[TN];
                    *(float4*)&a[0]  = *(const float4*)&As[kk * 128 + ty * TM];
                    *(float4*)&a[4]  = *(const float4*)&As[kk * 128 + ty * TM + 4];
                    *(float4*)&bb[0] = *(const float4*)&Bs[kk * 128 + tx * TN];
                    *(float4*)&bb[4] = *(const float4*)&Bs[kk * 128 + tx * TN + 4];
#pragma unroll
                    for (int i = 0; i < TM; i++)
#pragma unroll
                        for (int j = 0; j < TN; j++)
                            acc[i][j] = fmaf(a[i], bb[j], acc[i][j]);
                }
            }
            const int row0 = by * 256 + mh * 128 + ty * TM;
            const int col0 = nh * 128 + tx * TN;
#pragma unroll
            for (int i = 0; i < TM; i++)
#pragma unroll
                for (int j = 0; j < TN; j++) {
                    float v = acc[i][j] + bias[col0 + j];
                    int m = row0 + i, n = col0 + j;
                    if (two_pass)
                        C[qk_blk_off(m >> 7, n >> 5, m & 127, n & 31)] = to_tf32(v);
                    else
                        C[(size_t)m * kD + n] = v;
                }
            __syncthreads();
        }
    }
#endif
}

// ---------------------------------------------------------------------------
// Scores GEMM: E[b,m,n] = exp((q.k)/16) * maskfac(n)  stored bf16,
// plus row-sum partials rpart[nx][b][m].
// BM=256 (dual TMEM accumulators), BN=256, 3-stage cp.async.bulk pipeline.
// ---------------------------------------------------------------------------
static constexpr int SC_STAGE = 65536;
static constexpr int SC_SMEM = 4096 + 3 * SC_STAGE;   // 200704

__global__ __launch_bounds__(256)
void score_gemm(const float* __restrict__ Qb, const float* __restrict__ Kb,
                const int* __restrict__ mask, __nv_bfloat16* __restrict__ E,
                float* __restrict__ rpart, float scale)
{
    extern __shared__ __align__(1024) char smem[];
    const int tid = threadIdx.x;
    const int bz = blockIdx.z;
    __nv_bfloat16* C = E + (size_t)bz * kS * kS;
    const int* mk = mask + (size_t)bz * kS;

    const int my = blockIdx.y;
    const int nx = blockIdx.x;
    const int bm = my * 256;
    const int bn = nx * 256;

#if HAS_TCGEN05
    const uint32_t sb = smem_to_u32_gen(smem);
    const uint32_t m_done = sb + 48;
    float* s_mf = (float*)(smem + 64);
    const int wid = tid >> 5;

    if (wid == 0) { TCGEN05_ALLOC(sb + 56, 512); TCGEN05_RELINQUISH(); }
    if (tid == 0) {
#pragma unroll
        for (int s = 0; s < 3; s++) {
            MBARRIER_INIT(sb + s * 8, 1);
            MBARRIER_INIT(sb + 24 + s * 8, 1);
        }
        MBARRIER_INIT(m_done, 1);
    }
    s_mf[tid] = (mk[bn + tid] != 0) ? 1.0f : 0.0f;
    __syncthreads();
    const uint32_t tmem = *(volatile uint32_t*)(smem + 56);

    uint64_t dA0[3], dA1[3], dB[3];
#pragma unroll
    for (int s = 0; s < 3; s++) {
        uint32_t base = sb + 4096 + s * SC_STAGE;
        dA0[s] = MAKE_SMEM_DESC(base);
        dA1[s] = MAKE_SMEM_DESC(base + 16384);
        dB[s]  = MAKE_SMEM_DESC(base + 32768);
    }

    const int amt0 = bz * 16 + my * 2;
    const int bmt0 = bz * 16 + nx * 2;

    if (wid == 1) {
        if (elect_one_pred()) {
            for (int c = 0; c < 8; c++) {
                const int s = c % 3;
                const int w = c / 3;
                const uint32_t m_full = sb + s * 8;
                const uint32_t m_emp  = sb + 24 + s * 8;
                const uint32_t st = sb + 4096 + s * SC_STAGE;
                MBARRIER_WAIT_PARITY(m_emp, 1 ^ (w & 1));
                MBARRIER_EXPECT_TX(m_full, SC_STAGE);
                CP_ASYNC_BULK(st,
                              Qb + (((size_t)amt0 * 8 + c) << 12), 16384, m_full);
                CP_ASYNC_BULK(st + 16384,
                              Qb + (((size_t)(amt0 + 1) * 8 + c) << 12), 16384, m_full);
                CP_ASYNC_BULK(st + 32768,
                              Kb + (((size_t)bmt0 * 8 + c) << 12), 16384, m_full);
                CP_ASYNC_BULK(st + 49152,
                              Kb + (((size_t)(bmt0 + 1) * 8 + c) << 12), 16384, m_full);
            }
        }
    } else if (wid == 0) {
        if (elect_one_pred()) {
            for (int c = 0; c < 8; c++) {
                const int s = c % 3;
                const int w = c / 3;
                const uint32_t m_full = sb + s * 8;
                const uint32_t m_emp  = sb + 24 + s * 8;
                MBARRIER_WAIT_PARITY(m_full, w & 1);
#pragma unroll
                for (int k = 0; k < 4; k++)
                    TCGEN05_MMA_TF32_SS(tmem, dA0[s] + k * 2, dB[s] + k * 2,
                                        IDESC_128x256, (c > 0) || (k > 0));
#pragma unroll
                for (int k = 0; k < 4; k++)
                    TCGEN05_MMA_TF32_SS(tmem + 256, dA1[s] + k * 2, dB[s] + k * 2,
                                        IDESC_128x256, (c > 0) || (k > 0));
                TCGEN05_COMMIT(m_emp);
            }
            TCGEN05_COMMIT(m_done);
        }
    }

    MBARRIER_WAIT_PARITY(m_done, 0);
    TCGEN05_FENCE_AFTER();

    {
        const int lane = tid & 31;
        const int half = wid >> 2;
        const int m = bm + half * 128 + (wid & 3) * 32 + lane;
        const uint32_t tbase = tmem + half * 256;
        __nv_bfloat16* crow = C + (size_t)m * kS + bn;
        float rs = 0.0f;
#pragma unroll
        for (int g = 0; g < 8; g++) {
            uint32_t r[32];
            TCGEN05_LD_32X32B_X32(r, tbase + g * 32);
            TCGEN05_WAIT_LD();
            const int col0 = g * 32;
            float e[32];
#pragma unroll
            for (int j = 0; j < 32; j++) {
                e[j] = __expf(__uint_as_float(r[j]) * scale) * s_mf[col0 + j];
                rs += e[j];
            }
            uint32_t pk[16];
#pragma unroll
            for (int j = 0; j < 16; j++)
                pk[j] = pack_bf16x2(e[j * 2], e[j * 2 + 1]);
#pragma unroll
            for (int j = 0; j < 4; j++)
                *(uint4*)&crow[col0 + j * 8] = *(uint4*)&pk[j * 4];
        }
        rpart[((size_t)nx * kB + bz) * kS + m] = rs;
    }
    __syncthreads();
    if (wid == 0) TCGEN05_DEALLOC(tmem, 512);

#else
    // SIMT fallback — reads blocked Q/K layout, writes bf16 E + rpart.
    constexpr int BK = 16, TM = 8, TN = 8;
    float* As = (float*)smem;
    float* Bs = As + BK * 128;
    const int tx = tid & 15, ty = tid >> 4;
    const int amt0 = bz * 16 + my * 2;
    const int bmt0 = bz * 16 + nx * 2;

    for (int mh = 0; mh < 2; mh++) {
        const int amt = amt0 + mh;
        float rs[TM];
#pragma unroll
        for (int i = 0; i < TM; i++) rs[i] = 0.0f;

        for (int nh = 0; nh < 2; nh++) {
            const int bmtl = bmt0 + nh;
            float acc[TM][TN];
#pragma unroll
            for (int i = 0; i < TM; i++)
#pragma unroll
                for (int j = 0; j < TN; j++) acc[i][j] = 0.0f;

            for (int k0 = 0; k0 < kD; k0 += BK) {
                __syncthreads();
                for (int li = tid; li < 128 * BK; li += 256) {
                    int row = li / BK, kc = li % BK;
                    As[kc * 128 + row] =
                        Qb[qk_blk_off(amt, (k0 + kc) >> 5, row, (k0 + kc) & 31)];
                    Bs[kc * 128 + row] =
                        Kb[qk_blk_off(bmtl, (k0 + kc) >> 5, row, (k0 + kc) & 31)];
                }
                __syncthreads();
#pragma unroll
                for (int kk = 0; kk < BK; kk++) {
                    float a[TM], bb[TN];
                    *(float4*)&a[0]  = *(const float4*)&As[kk * 128 + ty * TM];
                    *(float4*)&a[4]  = *(const float4*)&As[kk * 128 + ty * TM + 4];
                    *(float4*)&bb[0] = *(const float4*)&Bs[kk * 128 + tx * TN];
                    *(float4*)&bb[4] = *(const float4*)&Bs[kk * 128 + tx * TN + 4];
#pragma unroll
                    for (int i = 0; i < TM; i++)
#pragma unroll
                        for (int j = 0; j < TN; j++)
                            acc[i][j] = fmaf(a[i], bb[j], acc[i][j]);
                }
            }
            const int row0 = bm + mh * 128 + ty * TM;
            const int col0 = bn + nh * 128 + tx * TN;
#pragma unroll
            for (int i = 0; i < TM; i++)
#pragma unroll
                for (int j = 0; j < TN; j++) {
                    float e = __expf(acc[i][j] * scale)
                              * ((mk[col0 + j] != 0) ? 1.0f : 0.0f);
                    C[(size_t)(row0 + i) * kS + col0 + j] = __float2bfloat16(e);
                    rs[i] += e;
                }
            __syncthreads();
        }
#pragma unroll
        for (int i = 0; i < TM; i++) {
            float v = rs[i];
#pragma unroll
            for (int o = 8; o; o >>= 1) v += __shfl_xor_sync(0xffffffffu, v, o);
            if (tx == 0)
                rpart[((size_t)nx * kB + bz) * kS + bm + mh * 128 + ty * TM + i] = v;
        }
    }
#endif
}

// ---------------------------------------------------------------------------
// invr[b,q] = 1 / sum_nx rpart[nx][b][q]
// ---------------------------------------------------------------------------
__global__ __launch_bounds__(256)
void rowsum_reduce_kernel(const float* __restrict__ rpart, float* __restrict__ invr)
{
    const int i = blockIdx.x * 256 + threadIdx.x;
    float s = 0.0f;
#pragma unroll
    for (int c = 0; c < NXT; c++) s += rpart[(size_t)c * (kB * kS) + i];
    invr[i] = 1.0f / s;
}

// ---------------------------------------------------------------------------
// Column-sum stream over bf16 E: wpart += E[b,q,k] * invr[b,q]. No barriers.
// ---------------------------------------------------------------------------
__global__ __launch_bounds__(256)
void colsum_stream_kernel(const __nv_bfloat16* __restrict__ E,
                          const float* __restrict__ invr,
                          float* __restrict__ wpart)
{
    const int ch = blockIdx.x;
    const int b  = blockIdx.y;
    const int tid = threadIdx.x;
    const __nv_bfloat16* base = E + ((size_t)b * kS + (size_t)ch * 32) * kS;
    const float* iv = invr + (size_t)b * kS + (size_t)ch * 32;

    float wacc[8];
#pragma unroll
    for (int i = 0; i < 8; i++) wacc[i] = 0.0f;

    for (int r = 0; r < 32; r++) {
        const float s = iv[r];
        const __nv_bfloat16* p = base + (size_t)r * kS + tid * 8;
        uint4 v = *(const uint4*)p;
        const uint32_t pk[4] = {v.x, v.y, v.z, v.w};
#pragma unroll
        for (int i = 0; i < 4; i++) {
            float2 f = __bfloat1622float2(*(const __nv_bfloat162*)&pk[i]);
            wacc[i * 2]     = fmaf(f.x, s, wacc[i * 2]);
            wacc[i * 2 + 1] = fmaf(f.y, s, wacc[i * 2 + 1]);
        }
    }

    float* o = wpart + (size_t)ch * (kB * kS) + (size_t)b * kS + tid * 8;
    *(float4*)&o[0] = make_float4(wacc[0], wacc[1], wacc[2], wacc[3]);
    *(float4*)&o[4] = make_float4(wacc[4], wacc[5], wacc[6], wacc[7]);
}

__global__ __launch_bounds__(256)
void colsum_reduce_kernel(const float* __restrict__ wpart, float* __restrict__ w)
{
    const int i = blockIdx.x * 256 + threadIdx.x;
    float s = 0.0f;
#pragma unroll
    for (int c = 0; c < QCH; c++) s += wpart[(size_t)c * (kB * kS) + i];
    w[i] = s;
}

__global__ __launch_bounds__(256)
void out_part_kernel(const float* __restrict__ w, const float* __restrict__ V,
                     float* __restrict__ opart)
{
    const int chunk = blockIdx.x;
    const int b     = blockIdx.y;
    const int d     = threadIdx.x;
    const float* vb = V + ((size_t)b * kS + (size_t)chunk * 64) * kD;
    const float* wb = w + b * kS + chunk * 64;
    float s = 0.0f;
#pragma unroll
    for (int k = 0; k < 64; k++) s = fmaf(wb[k], vb[(size_t)k * kD + d], s);
    opart[(size_t)(chunk * kB + b) * kD + d] = s;
}

__global__ __launch_bounds__(256)
void out_reduce_kernel(const float* __restrict__ opart, float* __restrict__ out)
{
    const int i = blockIdx.x * 256 + threadIdx.x;
    float s = 0.0f;
#pragma unroll
    for (int c = 0; c < N_KCHUNK; c++) s += opart[(size_t)c * (kB * kD) + i];
    out[i] = s * (1.0f / (float)kS);
}

// ---------------------------------------------------------------------------
// Launch
// ---------------------------------------------------------------------------
extern "C" void kernel_launch(void* const* d_in, const int* in_sizes, int n_in,
                              void* d_out, int out_size)
{
    const float* nodes = (const float*)d_in[0];
    const int*   mask  = (const int*)  d_in[1];
    const float* Wq    = (const float*)d_in[2];
    const float* bq    = (const float*)d_in[3];
    const float* Wk    = (const float*)d_in[4];
    const float* bk    = (const float*)d_in[5];
    const float* Wv    = (const float*)d_in[6];
    const float* bv    = (const float*)d_in[7];
    float* out = (float*)d_out;

    float *Nb, *Wh, *Wl, *Qb, *Kb, *V, *rpart, *invr, *w, *wpart, *opart;
    __nv_bfloat16* E;
    cudaGetSymbolAddress((void**)&Nb,    g_Nb);
    cudaGetSymbolAddress((void**)&Wh,    g_Wh);
    cudaGetSymbolAddress((void**)&Wl,    g_Wl);
    cudaGetSymbolAddress((void**)&Qb,    g_Qb);
    cudaGetSymbolAddress((void**)&Kb,    g_Kb);
    cudaGetSymbolAddress((void**)&V,     g_V);
    cudaGetSymbolAddress((void**)&E,     g_E);
    cudaGetSymbolAddress((void**)&rpart, g_rpart);
    cudaGetSymbolAddress((void**)&invr,  g_invr);
    cudaGetSymbolAddress((void**)&w,     g_w);
    cudaGetSymbolAddress((void**)&wpart, g_wpart);
    cudaGetSymbolAddress((void**)&opart, g_opart);

    cudaFuncSetAttribute(proj_gemm,
                         cudaFuncAttributeMaxDynamicSharedMemorySize, PJ_SMEM);
    cudaFuncSetAttribute(score_gemm,
                         cudaFuncAttributeMaxDynamicSharedMemorySize, SC_SMEM);

    dim3 blk(256);

    // 0. Prep: nodes -> blocked tf32; weights -> blocked hi/lo split.
    nodes_prep<<<dim3(8, kM / 128), blk>>>(nodes, Nb);
    wsplit_prep<<<dim3(8, 2, 3), blk>>>(Wq, Wk, Wv, Wh, Wl);

    // 1. Projections (pipelined, 2-pass q/k, 1-pass v): grid (3, 64).
    dim3 gproj(3, kM / 256, 1);
    proj_gemm<<<gproj, blk, PJ_SMEM>>>(Nb, Wh, Wl, bq, bk, bv, Qb, Kb, V);

    // 2. Scores -> E = exp(score/16) bf16 (masked = 0) + rowsum partials
    dim3 gsc(kS / 256, kS / 256, kB);
    score_gemm<<<gsc, blk, SC_SMEM>>>(Qb, Kb, mask, E, rpart, 0.0625f);

    // 3. rowsum -> invr, stream colsum, reduce, output contraction
    rowsum_reduce_kernel<<<(kB * kS) / 256, blk>>>(rpart, invr);
    colsum_stream_kernel<<<dim3(QCH, kB), blk>>>(E, invr, wpart);
    colsum_reduce_kernel<<<(kB * kS) / 256, blk>>>(wpart, w);
    out_part_kernel<<<dim3(N_KCHUNK, kB), blk>>>(w, V, opart);
    out_reduce_kernel<<<(kB * kD) / 256, blk>>>(opart, out);
}

// round 11
// speedup vs baseline: 2.0906x; 1.0620x over previous
#include <cuda_runtime.h>
#include <cuda_bf16.h>
#include <cstdint>
#include <math.h>

// ---------------------------------------------------------------------------
// Problem constants
// ---------------------------------------------------------------------------
static constexpr int kB = 8;
static constexpr int kS = 2048;
static constexpr int kD = 256;
static constexpr int kM = kB * kS;
static constexpr int QCH = 64;       // colsum: 32 rows per chunk
static constexpr int N_KCHUNK = 32;  // output split over keys
static constexpr int NXT = kS / 256; // 8 n-tiles per batch row

// Scratch (static device memory)
// Blocked layout: block = [128 rows x 32 cols] = 16KB, SW128-swizzled.
__device__ float g_Nb[kM * kD];                        // tf32-rounded nodes, blocked
__device__ float g_Wh[3 * kD * kD];                    // weight hi, blocked (q,k,v)
__device__ float g_Wl[2 * kD * kD];                    // weight lo, blocked (q,k)
__device__ float g_Qb[kB * kS * kD];                   // tf32 q, blocked
__device__ float g_Kb[kB * kS * kD];                   // tf32 k, blocked
__device__ float g_V[kB * kS * kD];                    // fp32 v, row-major
__device__ __nv_bfloat16 g_E[(size_t)kB * kS * kS];    // exp scores (bf16)
__device__ float g_rpart[NXT * kB * kS];
__device__ float g_invr[kB * kS];
__device__ float g_wpart[QCH * kB * kS];
__device__ float g_opart[N_KCHUNK * kB * kD];

#if defined(__CUDA_ARCH__) && defined(__CUDA_ARCH_FEAT_SM103_ALL)
#define HAS_TCGEN05 1
#else
#define HAS_TCGEN05 0
#endif

#define SMEM_SWIZZLE_128B(byte_offset) \
    ((byte_offset) ^ (((byte_offset) >> 3) & 0x70))

__device__ __forceinline__ uint32_t smem_to_u32_gen(const void* p) {
    uint32_t a;
    asm("{ .reg .u64 t; cvta.to.shared.u64 t, %1; cvt.u32.u64 %0, t; }"
        : "=r"(a) : "l"(p));
    return a;
}

__device__ __forceinline__ float to_tf32(float x) {
    float y;
    asm("cvt.rna.tf32.f32 %0, %1;" : "=f"(y) : "f"(x));
    return y;
}

__device__ __forceinline__ uint32_t pack_bf16x2(float lo, float hi) {
    uint32_t r;
    asm("cvt.rn.bf16x2.f32 %0, %1, %2;" : "=r"(r) : "f"(hi), "f"(lo));
    return r;
}

// float-index offset of element (r in [0,128), c in [0,32)) in blocked layout
__device__ __forceinline__ size_t qk_blk_off(int gmtile, int kchunk, int r, int c) {
    uint32_t byte = (uint32_t)(r * 128 + (c >> 2) * 16);
    uint32_t sw = SMEM_SWIZZLE_128B(byte) + (uint32_t)(c & 3) * 4;
    return ((size_t)(gmtile * 8 + kchunk) << 12) + (sw >> 2);
}

#if HAS_TCGEN05
__device__ __forceinline__ uint32_t elect_one_pred() {
    uint32_t pred;
    asm volatile(
        "{\n\t.reg .pred p;\n\t"
        "elect.sync _|p, 0xFFFFFFFF;\n\t"
        "selp.b32 %0, 1, 0, p;\n\t}"
        : "=r"(pred));
    return pred;
}

#define TCGEN05_ALLOC(smem_result_addr, nCols) \
    asm volatile("tcgen05.alloc.cta_group::1.sync.aligned.shared::cta.b32 [%0], %1;" \
                 :: "r"((uint32_t)(smem_result_addr)), "r"((uint32_t)(nCols)) : "memory")
#define TCGEN05_DEALLOC(tmem_addr, nCols) \
    asm volatile("tcgen05.dealloc.cta_group::1.sync.aligned.b32 %0, %1;" \
                 :: "r"(tmem_addr), "r"((uint32_t)(nCols)))
#define TCGEN05_RELINQUISH() \
    asm volatile("tcgen05.relinquish_alloc_permit.cta_group::1.sync.aligned;")
#define TCGEN05_COMMIT(mbar_smem_addr) \
    asm volatile("tcgen05.commit.cta_group::1.mbarrier::arrive::one.shared::cluster.b64 [%0];" \
                 :: "r"((uint32_t)(mbar_smem_addr)) : "memory")
#define TCGEN05_FENCE_AFTER() \
    asm volatile("tcgen05.fence::after_thread_sync;" ::: "memory")
#define TCGEN05_WAIT_LD() \
    asm volatile("tcgen05.wait::ld.sync.aligned;" ::: "memory")
#define MBARRIER_INIT(mbar_smem_addr, count) \
    asm volatile("mbarrier.init.shared.b64 [%0], %1;" \
                 :: "r"((uint32_t)(mbar_smem_addr)), "r"((uint32_t)(count)) : "memory")
#define MBARRIER_EXPECT_TX(mbar_smem_addr, tx_bytes) \
    asm volatile("mbarrier.arrive.expect_tx.shared.b64 _, [%0], %1;" \
                 :: "r"((uint32_t)(mbar_smem_addr)), "r"((uint32_t)(tx_bytes)) : "memory")

#define MBARRIER_WAIT_PARITY(mbar_smem_addr, phase_parity) do { \
    uint32_t _mbar = (uint32_t)(mbar_smem_addr); \
    uint32_t _parity = (uint32_t)(phase_parity); \
    uint32_t _done; \
    asm volatile( \
        "{\n\t.reg .pred p;\n\t" \
        "mbarrier.try_wait.parity.acquire.cta.shared::cta.b64 p, [%1], %2;\n\t" \
        "selp.b32 %0, 1, 0, p;\n\t}" \
        : "=r"(_done) : "r"(_mbar), "r"(_parity) : "memory"); \
    if (!_done) { \
        asm volatile( \
            "{\n\t.reg .pred P1;\n\t" \
            "WAIT_LOOP_%=:\n\t" \
            "mbarrier.try_wait.parity.acquire.cta.shared::cta.b64 P1, [%0], %1, 0x989680;\n\t" \
            "@P1 bra.uni WAIT_DONE_%=;\n\t" \
            "bra.uni WAIT_LOOP_%=;\n\t" \
            "WAIT_DONE_%=:\n\t}" \
            :: "r"(_mbar), "r"(_parity) : "memory"); \
    } \
} while(0)

#define TCGEN05_LD_32X32B_X32(r, tmem_addr) \
    asm volatile( \
        "tcgen05.ld.sync.aligned.32x32b.x32.b32 " \
        "{%0, %1, %2, %3, %4, %5, %6, %7, " \
        " %8, %9, %10, %11, %12, %13, %14, %15, " \
        " %16, %17, %18, %19, %20, %21, %22, %23, " \
        " %24, %25, %26, %27, %28, %29, %30, %31}, [%32];" \
        : "=r"((r)[0]),  "=r"((r)[1]),  "=r"((r)[2]),  "=r"((r)[3]), \
          "=r"((r)[4]),  "=r"((r)[5]),  "=r"((r)[6]),  "=r"((r)[7]), \
          "=r"((r)[8]),  "=r"((r)[9]),  "=r"((r)[10]), "=r"((r)[11]), \
          "=r"((r)[12]), "=r"((r)[13]), "=r"((r)[14]), "=r"((r)[15]), \
          "=r"((r)[16]), "=r"((r)[17]), "=r"((r)[18]), "=r"((r)[19]), \
          "=r"((r)[20]), "=r"((r)[21]), "=r"((r)[22]), "=r"((r)[23]), \
          "=r"((r)[24]), "=r"((r)[25]), "=r"((r)[26]), "=r"((r)[27]), \
          "=r"((r)[28]), "=r"((r)[29]), "=r"((r)[30]), "=r"((r)[31]) \
        : "r"(tmem_addr))

#define TCGEN05_MMA_TF32_SS(d_tmem, a_desc, b_desc, idesc, enable_d) do { \
    uint32_t _en = (enable_d) ? 1u : 0u; \
    uint32_t _zero = 0u; \
    asm volatile( \
        "{\n\t.reg .pred p;\n\t" \
        "setp.ne.u32 p, %5, 0;\n\t" \
        "tcgen05.mma.cta_group::1.kind::tf32 [%0], %1, %2, %3, {%4, %4, %4, %4}, p;\n\t" \
        "}" \
        :: "r"(d_tmem), "l"(a_desc), "l"(b_desc), "r"(idesc), "r"(_zero), "r"(_en) \
        : "memory"); \
} while(0)

static constexpr uint64_t SMEM_DESC_BASE_SW128 =
    (uint64_t(2)  << 61) | (uint64_t(1) << 46) | (uint64_t(64) << 32) | (uint64_t(1) << 16);
#define MAKE_SMEM_DESC(base_addr) \
    (SMEM_DESC_BASE_SW128 | ((uint64_t)((base_addr) >> 4) & 0x3FFF))

#define CP_ASYNC_BULK(dst_smem, src_gmem, bytes, mbar) \
    asm volatile("cp.async.bulk.shared::cta.global.mbarrier::complete_tx::bytes " \
                 "[%0], [%1], %2, [%3];" \
                 :: "r"((uint32_t)(dst_smem)), "l"(src_gmem), \
                    "r"((uint32_t)(bytes)), "r"((uint32_t)(mbar)) : "memory")

// IDESC: tf32, F32 accum
static constexpr uint32_t IDESC_128x256 =
    (1u << 4) | (2u << 7) | (2u << 10) | ((256 / 8) << 17) | ((128 / 16) << 24);
static constexpr uint32_t IDESC_128x128 =
    (1u << 4) | (2u << 7) | (2u << 10) | ((128 / 8) << 17) | ((128 / 16) << 24);
#endif  // HAS_TCGEN05

// ---------------------------------------------------------------------------
// Prep 1: nodes -> tf32-rounded, blocked-swizzled. grid (8, kM/128).
// ---------------------------------------------------------------------------
__global__ __launch_bounds__(256)
void nodes_prep(const float* __restrict__ src, float* __restrict__ Nb)
{
    const int kc = blockIdx.x;
    const int mt = blockIdx.y;
    const int tid = threadIdx.x;
    float* blk = Nb + (((size_t)mt * 8 + kc) << 12);
#pragma unroll
    for (int t = 0; t < 4; t++) {
        int idx = tid + t * 256;
        int row = idx >> 3, c4 = idx & 7;
        float4 v = *(const float4*)(src + (size_t)(mt * 128 + row) * kD + kc * 32 + c4 * 4);
        v.x = to_tf32(v.x); v.y = to_tf32(v.y);
        v.z = to_tf32(v.z); v.w = to_tf32(v.w);
        uint32_t sw = SMEM_SWIZZLE_128B((uint32_t)(row * 128 + c4 * 16));
        *(float4*)((char*)blk + sw) = v;
    }
}

// ---------------------------------------------------------------------------
// Prep 2: weights -> (hi, lo) tf32 split, blocked. grid (8, 2, 3).
// ---------------------------------------------------------------------------
__global__ __launch_bounds__(256)
void wsplit_prep(const float* __restrict__ Wq, const float* __restrict__ Wk,
                 const float* __restrict__ Wv,
                 float* __restrict__ Wh, float* __restrict__ Wl)
{
    const int kc = blockIdx.x;
    const int mt = blockIdx.y;
    const int w  = blockIdx.z;
    const int tid = threadIdx.x;
    const float* W = (w == 0) ? Wq : (w == 1) ? Wk : Wv;
    float* bh = Wh + (size_t)w * (kD * kD) + (((size_t)mt * 8 + kc) << 12);
    float* bl = (w < 2) ? Wl + (size_t)w * (kD * kD) + (((size_t)mt * 8 + kc) << 12)
                        : nullptr;
#pragma unroll
    for (int t = 0; t < 4; t++) {
        int idx = tid + t * 256;
        int row = idx >> 3, c4 = idx & 7;
        float4 v = *(const float4*)(W + (size_t)(mt * 128 + row) * kD + kc * 32 + c4 * 4);
        float4 h, l;
        h.x = to_tf32(v.x); l.x = to_tf32(v.x - h.x);
        h.y = to_tf32(v.y); l.y = to_tf32(v.y - h.y);
        h.z = to_tf32(v.z); l.z = to_tf32(v.z - h.z);
        h.w = to_tf32(v.w); l.w = to_tf32(v.w - h.w);
        uint32_t sw = SMEM_SWIZZLE_128B((uint32_t)(row * 128 + c4 * 16));
        *(float4*)((char*)bh + sw) = h;
        if (bl) *(float4*)((char*)bl + sw) = l;
    }
}

// ---------------------------------------------------------------------------
// Pipelined projection GEMM, BM=128, BN=128, grid (2 nx, 128 my, 3 w).
//   q/k (w<2): C = tf32( A @ (Wh+Wl)^T + bias ) -> blocked
//   v  (w=2): C = A @ Wh^T + bias               -> row-major fp32
// smem ctrl [0,2048): full0@0 full1@8 emp0@16 emp1@24 done@32 tmem@40
//                     bias[128] @1024
// stages: 2 x 48KB {A 16K | Bh 16K | Bl 16K}   total = 100352 -> 2 CTAs/SM
// ---------------------------------------------------------------------------
static constexpr int PJ_STAGE = 49152;
static constexpr int PJ_SMEM = 2048 + 2 * PJ_STAGE;   // 100352

__global__ __launch_bounds__(256)
void proj_gemm(const float* __restrict__ Nb,
               const float* __restrict__ Wh, const float* __restrict__ Wl,
               const float* __restrict__ b0, const float* __restrict__ b1,
               const float* __restrict__ b2,
               float* __restrict__ C0, float* __restrict__ C1,
               float* __restrict__ C2)
{
    extern __shared__ __align__(1024) char smem[];
    const int tid = threadIdx.x;
    const int nx = blockIdx.x;           // n tile of 128 cols
    const int my = blockIdx.y;           // m tile of 128 rows
    const int w  = blockIdx.z;           // 0=q, 1=k, 2=v
    const float* bias = (w == 0) ? b0 : (w == 1) ? b1 : b2;
    float* C = (w == 0) ? C0 : (w == 1) ? C1 : C2;
    const bool two_pass = (w < 2);
    const float* WhB = Wh + (size_t)w * (kD * kD);
    const float* WlB = Wl + (size_t)w * (kD * kD);
    const int bn = nx * 128;
    const int bm = my * 128;

#if HAS_TCGEN05
    const uint32_t sb = smem_to_u32_gen(smem);
    const uint32_t m_done = sb + 32;
    float* s_bias = (float*)(smem + 1024);
    const int wid = tid >> 5;

    if (wid == 0) { TCGEN05_ALLOC(sb + 40, 128); TCGEN05_RELINQUISH(); }
    if (tid == 0) {
        MBARRIER_INIT(sb + 0, 1);
        MBARRIER_INIT(sb + 8, 1);
        MBARRIER_INIT(sb + 16, 1);
        MBARRIER_INIT(sb + 24, 1);
        MBARRIER_INIT(m_done, 1);
    }
    if (tid < 128) s_bias[tid] = bias[bn + tid];
    __syncthreads();
    const uint32_t tmem = *(volatile uint32_t*)(smem + 40);

    uint64_t dA[2], dBh[2], dBl[2];
#pragma unroll
    for (int s = 0; s < 2; s++) {
        uint32_t base = sb + 2048 + s * PJ_STAGE;
        dA[s]  = MAKE_SMEM_DESC(base);
        dBh[s] = MAKE_SMEM_DESC(base + 16384);
        dBl[s] = MAKE_SMEM_DESC(base + 32768);
    }

    const uint32_t tx_bytes = two_pass ? 49152u : 32768u;

    if (wid == 1) {
        if (elect_one_pred()) {
            for (int c = 0; c < 8; c++) {
                const int s = c & 1;
                const int i = c >> 1;
                const uint32_t m_full = sb + s * 8;
                const uint32_t m_emp  = sb + 16 + s * 8;
                const uint32_t st = sb + 2048 + s * PJ_STAGE;
                MBARRIER_WAIT_PARITY(m_emp, 1 ^ (i & 1));
                MBARRIER_EXPECT_TX(m_full, tx_bytes);
                CP_ASYNC_BULK(st,
                              Nb + (((size_t)my * 8 + c) << 12), 16384, m_full);
                CP_ASYNC_BULK(st + 16384,
                              WhB + (((size_t)nx * 8 + c) << 12), 16384, m_full);
                if (two_pass)
                    CP_ASYNC_BULK(st + 32768,
                                  WlB + (((size_t)nx * 8 + c) << 12), 16384, m_full);
            }
        }
    } else if (wid == 0) {
        if (elect_one_pred()) {
            for (int c = 0; c < 8; c++) {
                const int s = c & 1;
                const int i = c >> 1;
                const uint32_t m_full = sb + s * 8;
                const uint32_t m_emp  = sb + 16 + s * 8;
                MBARRIER_WAIT_PARITY(m_full, i & 1);
#pragma unroll
                for (int k = 0; k < 4; k++)
                    TCGEN05_MMA_TF32_SS(tmem, dA[s] + k * 2, dBh[s] + k * 2,
                                        IDESC_128x128, (c > 0) || (k > 0));
                if (two_pass) {
#pragma unroll
                    for (int k = 0; k < 4; k++)
                        TCGEN05_MMA_TF32_SS(tmem, dA[s] + k * 2, dBl[s] + k * 2,
                                            IDESC_128x128, true);
                }
                TCGEN05_COMMIT(m_emp);
            }
            TCGEN05_COMMIT(m_done);
        }
    }

    MBARRIER_WAIT_PARITY(m_done, 0);
    TCGEN05_FENCE_AFTER();

    // Epilogue: warps 0-3 cols 0-63, warps 4-7 cols 64-127.
    {
        const int lane = tid & 31;
        const int half = wid >> 2;
        const int mloc = (wid & 3) * 32 + lane;
        const int m = bm + mloc;
#pragma unroll
        for (int g = 0; g < 2; g++) {
            const int col0 = half * 64 + g * 32;
            uint32_t r[32];
            TCGEN05_LD_32X32B_X32(r, tmem + col0);
            TCGEN05_WAIT_LD();
            if (two_pass) {
#pragma unroll
                for (int j = 0; j < 32; j++)
                    r[j] = __float_as_uint(
                        to_tf32(__uint_as_float(r[j]) + s_bias[col0 + j]));
                float* blk = C + (((size_t)(m >> 7) * 8 + nx * 4 + half * 2 + g) << 12);
#pragma unroll
                for (int j = 0; j < 8; j++) {
                    uint32_t sw = SMEM_SWIZZLE_128B((uint32_t)(mloc * 128 + j * 16));
                    *(float4*)((char*)blk + sw) = *(float4*)&r[j * 4];
                }
            } else {
#pragma unroll
                for (int j = 0; j < 32; j++)
                    r[j] = __float_as_uint(__uint_as_float(r[j]) + s_bias[col0 + j]);
                float* crow = C + (size_t)m * kD + bn + col0;
#pragma unroll
                for (int j = 0; j < 8; j++)
                    *(float4*)&crow[j * 4] = *(float4*)&r[j * 4];
            }
        }
    }
    __syncthreads();
    if (wid == 0) TCGEN05_DEALLOC(tmem, 128);

#else
    // SIMT fallback — reads blocked Nb / Wh / Wl.
    constexpr int BK = 16, TM = 8, TN = 8;
    float* As = (float*)smem;
    float* Bs = As + BK * 128;
    const int tx = tid & 15, ty = tid >> 4;

    float acc[TM][TN];
#pragma unroll
    for (int i = 0; i < TM; i++)
#pragma unroll
        for (int j = 0; j < TN; j++) acc[i][j] = 0.0f;

    for (int k0 = 0; k0 < kD; k0 += BK) {
        __syncthreads();
        for (int li = tid; li < 128 * BK; li += 256) {
            int row = li / BK, kc = li % BK;
            size_t off = qk_blk_off(nx, (k0 + kc) >> 5, row, (k0 + kc) & 31);
            As[kc * 128 + row] =
                Nb[qk_blk_off(my, (k0 + kc) >> 5, row, (k0 + kc) & 31)];
            float bw = WhB[off];
            if (two_pass) bw += WlB[off];
            Bs[kc * 128 + row] = bw;
        }
        __syncthreads();
#pragma unroll
        for (int kk = 0; kk < BK; kk++) {
            float a[TM], bb[TN];
            *(float4*)&a[0]  = *(const float4*)&As[kk * 128 + ty * TM];
            *(float4*)&a[4]  = *(const float4*)&As[kk * 128 + ty * TM + 4];
            *(float4*)&bb[0] = *(const float4*)&Bs[kk * 128 + tx * TN];
            *(float4*)&bb[4] = *(const float4*)&Bs[kk * 128 + tx * TN + 4];
#pragma unroll
            for (int i = 0; i < TM; i++)
#pragma unroll
                for (int j = 0; j < TN; j++)
                    acc[i][j] = fmaf(a[i], bb[j], acc[i][j]);
        }
    }
    const int row0 = bm + ty * TM, col0 = bn + tx * TN;
#pragma unroll
    for (int i = 0; i < TM; i++)
#pragma unroll
        for (int j = 0; j < TN; j++) {
            float v = acc[i][j] + bias[col0 + j];
            int m = row0 + i, n = col0 + j;
            if (two_pass)
                C[qk_blk_off(m >> 7, n >> 5, m & 127, n & 31)] = to_tf32(v);
            else
                C[(size_t)m * kD + n] = v;
        }
#endif
}

// ---------------------------------------------------------------------------
// Scores GEMM: E[b,m,n] = exp((q.k)/16) * maskfac(n)  bf16, + rowsum partials.
// BM=128, BN=256, 2-stage bulk pipeline. grid (8 nx, 16 my, 8 bz).
// smem ctrl [0,2048): full0@0 full1@8 emp0@16 emp1@24 done@32 tmem@40
//                     rs2[128] @256, maskf[256] @1024
// stages: 2 x 48KB {Q 16K | K 32K}    total 100352 -> 2 CTAs/SM
// ---------------------------------------------------------------------------
static constexpr int SC_STAGE = 49152;
static constexpr int SC_SMEM = 2048 + 2 * SC_STAGE;   // 100352

__global__ __launch_bounds__(256)
void score_gemm(const float* __restrict__ Qb, const float* __restrict__ Kb,
                const int* __restrict__ mask, __nv_bfloat16* __restrict__ E,
                float* __restrict__ rpart, float scale)
{
    extern __shared__ __align__(1024) char smem[];
    const int tid = threadIdx.x;
    const int bz = blockIdx.z;
    __nv_bfloat16* C = E + (size_t)bz * kS * kS;
    const int* mk = mask + (size_t)bz * kS;

    const int my = blockIdx.y;          // m tile (128 rows)
    const int nx = blockIdx.x;          // n tile (256 cols)
    const int bm = my * 128;
    const int bn = nx * 256;

#if HAS_TCGEN05
    const uint32_t sb = smem_to_u32_gen(smem);
    const uint32_t m_done = sb + 32;
    float* s_rs2 = (float*)(smem + 256);
    float* s_mf  = (float*)(smem + 1024);
    const int wid = tid >> 5;

    if (wid == 0) { TCGEN05_ALLOC(sb + 40, 256); TCGEN05_RELINQUISH(); }
    if (tid == 0) {
        MBARRIER_INIT(sb + 0, 1);
        MBARRIER_INIT(sb + 8, 1);
        MBARRIER_INIT(sb + 16, 1);
        MBARRIER_INIT(sb + 24, 1);
        MBARRIER_INIT(m_done, 1);
    }
    s_mf[tid] = (mk[bn + tid] != 0) ? 1.0f : 0.0f;
    __syncthreads();
    const uint32_t tmem = *(volatile uint32_t*)(smem + 40);

    uint64_t dA[2], dB[2];
#pragma unroll
    for (int s = 0; s < 2; s++) {
        uint32_t base = sb + 2048 + s * SC_STAGE;
        dA[s] = MAKE_SMEM_DESC(base);
        dB[s] = MAKE_SMEM_DESC(base + 16384);
    }

    const int amt  = bz * 16 + my;
    const int bmt0 = bz * 16 + nx * 2;

    if (wid == 1) {
        if (elect_one_pred()) {
            for (int c = 0; c < 8; c++) {
                const int s = c & 1;
                const int i = c >> 1;
                const uint32_t m_full = sb + s * 8;
                const uint32_t m_emp  = sb + 16 + s * 8;
                const uint32_t st = sb + 2048 + s * SC_STAGE;
                MBARRIER_WAIT_PARITY(m_emp, 1 ^ (i & 1));
                MBARRIER_EXPECT_TX(m_full, SC_STAGE);
                CP_ASYNC_BULK(st,
                              Qb + (((size_t)amt * 8 + c) << 12), 16384, m_full);
                CP_ASYNC_BULK(st + 16384,
                              Kb + (((size_t)bmt0 * 8 + c) << 12), 16384, m_full);
                CP_ASYNC_BULK(st + 32768,
                              Kb + (((size_t)(bmt0 + 1) * 8 + c) << 12), 16384, m_full);
            }
        }
    } else if (wid == 0) {
        if (elect_one_pred()) {
            for (int c = 0; c < 8; c++) {
                const int s = c & 1;
                const int i = c >> 1;
                const uint32_t m_full = sb + s * 8;
                const uint32_t m_emp  = sb + 16 + s * 8;
                MBARRIER_WAIT_PARITY(m_full, i & 1);
#pragma unroll
                for (int k = 0; k < 4; k++)
                    TCGEN05_MMA_TF32_SS(tmem, dA[s] + k * 2, dB[s] + k * 2,
                                        IDESC_128x256, (c > 0) || (k > 0));
                TCGEN05_COMMIT(m_emp);
            }
            TCGEN05_COMMIT(m_done);
        }
    }

    MBARRIER_WAIT_PARITY(m_done, 0);
    TCGEN05_FENCE_AFTER();

    // Epilogue: warps 0-3 keys 0-127, warps 4-7 keys 128-255 (same q rows).
    {
        const int lane = tid & 31;
        const int half = wid >> 2;
        const int qrow = (wid & 3) * 32 + lane;
        const int m = bm + qrow;
        __nv_bfloat16* crow = C + (size_t)m * kS + bn + half * 128;
        float rs = 0.0f;
#pragma unroll
        for (int g = 0; g < 4; g++) {
            const int col0 = half * 128 + g * 32;
            uint32_t r[32];
            TCGEN05_LD_32X32B_X32(r, tmem + col0);
            TCGEN05_WAIT_LD();
            float e[32];
#pragma unroll
            for (int j = 0; j < 32; j++) {
                e[j] = __expf(__uint_as_float(r[j]) * scale) * s_mf[col0 + j];
                rs += e[j];
            }
            uint32_t pk[16];
#pragma unroll
            for (int j = 0; j < 16; j++)
                pk[j] = pack_bf16x2(e[j * 2], e[j * 2 + 1]);
#pragma unroll
            for (int j = 0; j < 4; j++)
                *(uint4*)&crow[g * 32 + j * 8] = *(uint4*)&pk[j * 4];
        }
        if (half == 1) s_rs2[qrow] = rs;
        __syncthreads();
        if (half == 0)
            rpart[((size_t)nx * kB + bz) * kS + m] = rs + s_rs2[qrow];
    }
    __syncthreads();
    if (wid == 0) TCGEN05_DEALLOC(tmem, 256);

#else
    // SIMT fallback — reads blocked Q/K layout, writes bf16 E + rpart.
    constexpr int BK = 16, TM = 8, TN = 8;
    float* As = (float*)smem;
    float* Bs = As + BK * 128;
    const int tx = tid & 15, ty = tid >> 4;
    const int amt  = bz * 16 + my;
    const int bmt0 = bz * 16 + nx * 2;

    float rs[TM];
#pragma unroll
    for (int i = 0; i < TM; i++) rs[i] = 0.0f;

    for (int nh = 0; nh < 2; nh++) {
        const int bmtl = bmt0 + nh;
        float acc[TM][TN];
#pragma unroll
        for (int i = 0; i < TM; i++)
#pragma unroll
            for (int j = 0; j < TN; j++) acc[i][j] = 0.0f;

        for (int k0 = 0; k0 < kD; k0 += BK) {
            __syncthreads();
            for (int li = tid; li < 128 * BK; li += 256) {
                int row = li / BK, kc = li % BK;
                As[kc * 128 + row] =
                    Qb[qk_blk_off(amt, (k0 + kc) >> 5, row, (k0 + kc) & 31)];
                Bs[kc * 128 + row] =
                    Kb[qk_blk_off(bmtl, (k0 + kc) >> 5, row, (k0 + kc) & 31)];
            }
            __syncthreads();
#pragma unroll
            for (int kk = 0; kk < BK; kk++) {
                float a[TM], bb[TN];
                *(float4*)&a[0]  = *(const float4*)&As[kk * 128 + ty * TM];
                *(float4*)&a[4]  = *(const float4*)&As[kk * 128 + ty * TM + 4];
                *(float4*)&bb[0] = *(const float4*)&Bs[kk * 128 + tx * TN];
                *(float4*)&bb[4] = *(const float4*)&Bs[kk * 128 + tx * TN + 4];
#pragma unroll
                for (int i = 0; i < TM; i++)
#pragma unroll
                    for (int j = 0; j < TN; j++)
                        acc[i][j] = fmaf(a[i], bb[j], acc[i][j]);
            }
        }
        const int row0 = bm + ty * TM;
        const int col0 = bn + nh * 128 + tx * TN;
#pragma unroll
        for (int i = 0; i < TM; i++)
#pragma unroll
            for (int j = 0; j < TN; j++) {
                float e = __expf(acc[i][j] * scale)
                          * ((mk[col0 + j] != 0) ? 1.0f : 0.0f);
                C[(size_t)(row0 + i) * kS + col0 + j] = __float2bfloat16(e);
                rs[i] += e;
            }
        __syncthreads();
    }
#pragma unroll
    for (int i = 0; i < TM; i++) {
        float v = rs[i];
#pragma unroll
        for (int o = 8; o; o >>= 1) v += __shfl_xor_sync(0xffffffffu, v, o);
        if (tx == 0)
            rpart[((size_t)nx * kB + bz) * kS + bm + ty * TM + i] = v;
    }
#endif
}

// ---------------------------------------------------------------------------
// invr[b,q] = 1 / sum_nx rpart[nx][b][q]
// ---------------------------------------------------------------------------
__global__ __launch_bounds__(256)
void rowsum_reduce_kernel(const float* __restrict__ rpart, float* __restrict__ invr)
{
    const int i = blockIdx.x * 256 + threadIdx.x;
    float s = 0.0f;
#pragma unroll
    for (int c = 0; c < NXT; c++) s += rpart[(size_t)c * (kB * kS) + i];
    invr[i] = 1.0f / s;
}

// ---------------------------------------------------------------------------
// Column-sum stream over bf16 E: wpart += E[b,q,k] * invr[b,q].
// ---------------------------------------------------------------------------
__global__ __launch_bounds__(256)
void colsum_stream_kernel(const __nv_bfloat16* __restrict__ E,
                          const float* __restrict__ invr,
                          float* __restrict__ wpart)
{
    const int ch = blockIdx.x;
    const int b  = blockIdx.y;
    const int tid = threadIdx.x;
    const __nv_bfloat16* base = E + ((size_t)b * kS + (size_t)ch * 32) * kS;
    const float* iv = invr + (size_t)b * kS + (size_t)ch * 32;

    float wacc[8];
#pragma unroll
    for (int i = 0; i < 8; i++) wacc[i] = 0.0f;

    for (int r = 0; r < 32; r++) {
        const float s = iv[r];
        const __nv_bfloat16* p = base + (size_t)r * kS + tid * 8;
        uint4 v = *(const uint4*)p;
        const uint32_t pk[4] = {v.x, v.y, v.z, v.w};
#pragma unroll
        for (int i = 0; i < 4; i++) {
            float2 f = __bfloat1622float2(*(const __nv_bfloat162*)&pk[i]);
            wacc[i * 2]     = fmaf(f.x, s, wacc[i * 2]);
            wacc[i * 2 + 1] = fmaf(f.y, s, wacc[i * 2 + 1]);
        }
    }

    float* o = wpart + (size_t)ch * (kB * kS) + (size_t)b * kS + tid * 8;
    *(float4*)&o[0] = make_float4(wacc[0], wacc[1], wacc[2], wacc[3]);
    *(float4*)&o[4] = make_float4(wacc[4], wacc[5], wacc[6], wacc[7]);
}

// ---------------------------------------------------------------------------
// out_part: w segment reduced from wpart in-block, then o = sum_k w_k V[k,d].
// grid (32 kchunk, 8 b), 256 threads.
// ---------------------------------------------------------------------------
__global__ __launch_bounds__(256)
void out_part_kernel(const float* __restrict__ wpart, const float* __restrict__ V,
                     float* __restrict__ opart)
{
    __shared__ float ws[64];
    const int chunk = blockIdx.x;
    const int b     = blockIdx.y;
    const int tid   = threadIdx.x;

    if (tid < 64) {
        const int key = chunk * 64 + tid;
        float s = 0.0f;
#pragma unroll 8
        for (int c = 0; c < QCH; c++)
            s += wpart[(size_t)c * (kB * kS) + (size_t)b * kS + key];
        ws[tid] = s;
    }
    __syncthreads();

    const float* vb = V + ((size_t)b * kS + (size_t)chunk * 64) * kD;
    float s = 0.0f;
#pragma unroll
    for (int k = 0; k < 64; k++) s = fmaf(ws[k], vb[(size_t)k * kD + tid], s);
    opart[(size_t)(chunk * kB + b) * kD + tid] = s;
}

__global__ __launch_bounds__(256)
void out_reduce_kernel(const float* __restrict__ opart, float* __restrict__ out)
{
    const int i = blockIdx.x * 256 + threadIdx.x;
    float s = 0.0f;
#pragma unroll
    for (int c = 0; c < N_KCHUNK; c++) s += opart[(size_t)c * (kB * kD) + i];
    out[i] = s * (1.0f / (float)kS);
}

// ---------------------------------------------------------------------------
// Launch
// ---------------------------------------------------------------------------
extern "C" void kernel_launch(void* const* d_in, const int* in_sizes, int n_in,
                              void* d_out, int out_size)
{
    const float* nodes = (const float*)d_in[0];
    const int*   mask  = (const int*)  d_in[1];
    const float* Wq    = (const float*)d_in[2];
    const float* bq    = (const float*)d_in[3];
    const float* Wk    = (const float*)d_in[4];
    const float* bk    = (const float*)d_in[5];
    const float* Wv    = (const float*)d_in[6];
    const float* bv    = (const float*)d_in[7];
    float* out = (float*)d_out;

    float *Nb, *Wh, *Wl, *Qb, *Kb, *V, *rpart, *invr, *wpart, *opart;
    __nv_bfloat16* E;
    cudaGetSymbolAddress((void**)&Nb,    g_Nb);
    cudaGetSymbolAddress((void**)&Wh,    g_Wh);
    cudaGetSymbolAddress((void**)&Wl,    g_Wl);
    cudaGetSymbolAddress((void**)&Qb,    g_Qb);
    cudaGetSymbolAddress((void**)&Kb,    g_Kb);
    cudaGetSymbolAddress((void**)&V,     g_V);
    cudaGetSymbolAddress((void**)&E,     g_E);
    cudaGetSymbolAddress((void**)&rpart, g_rpart);
    cudaGetSymbolAddress((void**)&invr,  g_invr);
    cudaGetSymbolAddress((void**)&wpart, g_wpart);
    cudaGetSymbolAddress((void**)&opart, g_opart);

    cudaFuncSetAttribute(proj_gemm,
                         cudaFuncAttributeMaxDynamicSharedMemorySize, PJ_SMEM);
    cudaFuncSetAttribute(score_gemm,
                         cudaFuncAttributeMaxDynamicSharedMemorySize, SC_SMEM);

    dim3 blk(256);

    // 0. Prep: nodes -> blocked tf32; weights -> blocked hi/lo split.
    nodes_prep<<<dim3(8, kM / 128), blk>>>(nodes, Nb);
    wsplit_prep<<<dim3(8, 2, 3), blk>>>(Wq, Wk, Wv, Wh, Wl);

    // 1. Projections: grid (2 nx, 128 my, 3 w), 2 CTAs/SM.
    dim3 gproj(2, kM / 128, 3);
    proj_gemm<<<gproj, blk, PJ_SMEM>>>(Nb, Wh, Wl, bq, bk, bv, Qb, Kb, V);

    // 2. Scores -> E = exp(score/16) bf16 (masked = 0) + rowsum partials.
    dim3 gsc(kS / 256, kS / 128, kB);
    score_gemm<<<gsc, blk, SC_SMEM>>>(Qb, Kb, mask, E, rpart, 0.0625f);

    // 3. rowsum -> invr, stream colsum, fused w-reduce + output contraction.
    rowsum_reduce_kernel<<<(kB * kS) / 256, blk>>>(rpart, invr);
    colsum_stream_kernel<<<dim3(QCH, kB), blk>>>(E, invr, wpart);
    out_part_kernel<<<dim3(N_KCHUNK, kB), blk>>>(wpart, V, opart);
    out_reduce_kernel<<<(kB * kD) / 256, blk>>>(opart, out);
}